// round 5
// baseline (speedup 1.0000x reference)
#include <cuda_runtime.h>
#include <cuda_bf16.h>
#include <cstdint>

#define B_ 16
#define S_ 2048
#define D_ 1024
#define H_ 128
#define M_TOT (B_*S_)

// ---------------- scratch (__device__ globals; allocation-free rule) -------
__device__ __nv_bfloat16 g_a_hi[(size_t)M_TOT * D_];
__device__ __nv_bfloat16 g_a_lo[(size_t)M_TOT * D_];
__device__ __nv_bfloat16 g_wt_hi[3 * H_ * D_];   // [z][n][k] (W transposed)
__device__ __nv_bfloat16 g_wt_lo[3 * H_ * D_];
__device__ __nv_bfloat16 g_qh[M_TOT * H_], g_ql[M_TOT * H_];
__device__ __nv_bfloat16 g_kh[M_TOT * H_], g_kl[M_TOT * H_];
__device__ __nv_bfloat16 g_vh[M_TOT * H_], g_vl[M_TOT * H_];

// ---------------- helpers (sm_80-baseline, family-target safe) -------------
__device__ __forceinline__ uint32_t smem_u32(const void* p) {
    uint32_t a;
    asm("{ .reg .u64 t; cvta.to.shared.u64 t, %1; cvt.u32.u64 %0, t; }"
        : "=r"(a) : "l"(p));
    return a;
}
__device__ __forceinline__ void cp16(uint32_t dst, const void* src) {
    asm volatile("cp.async.cg.shared.global [%0], [%1], 16;" :: "r"(dst), "l"(src));
}
#define CP_COMMIT() asm volatile("cp.async.commit_group;" ::: "memory")
#define CP_WAIT0()  asm volatile("cp.async.wait_group 0;" ::: "memory")
#define CP_WAIT1()  asm volatile("cp.async.wait_group 1;" ::: "memory")

__device__ __forceinline__ void ldsm_x4(uint32_t r[4], uint32_t addr) {
    asm volatile("ldmatrix.sync.aligned.m8n8.x4.shared.b16 {%0,%1,%2,%3}, [%4];"
        : "=r"(r[0]), "=r"(r[1]), "=r"(r[2]), "=r"(r[3]) : "r"(addr));
}
__device__ __forceinline__ void ldsm_x4_t(uint32_t r[4], uint32_t addr) {
    asm volatile("ldmatrix.sync.aligned.m8n8.x4.trans.shared.b16 {%0,%1,%2,%3}, [%4];"
        : "=r"(r[0]), "=r"(r[1]), "=r"(r[2]), "=r"(r[3]) : "r"(addr));
}
__device__ __forceinline__ void mma16816(float c[4], const uint32_t a[4],
                                         const uint32_t b[2]) {
    asm volatile("mma.sync.aligned.m16n8k16.row.col.f32.bf16.bf16.f32 "
        "{%0,%1,%2,%3}, {%4,%5,%6,%7}, {%8,%9}, {%0,%1,%2,%3};"
        : "+f"(c[0]), "+f"(c[1]), "+f"(c[2]), "+f"(c[3])
        : "r"(a[0]), "r"(a[1]), "r"(a[2]), "r"(a[3]), "r"(b[0]), "r"(b[1]));
}
__device__ __forceinline__ void split2(float x0, float x1, uint32_t& h, uint32_t& l) {
    __nv_bfloat16 h0 = __float2bfloat16(x0), h1 = __float2bfloat16(x1);
    __nv_bfloat162 hp = __halves2bfloat162(h0, h1);
    h = *(uint32_t*)&hp;
    __nv_bfloat16 l0 = __float2bfloat16(x0 - __bfloat162float(h0));
    __nv_bfloat16 l1 = __float2bfloat16(x1 - __bfloat162float(h1));
    __nv_bfloat162 lp = __halves2bfloat162(l0, l1);
    l = *(uint32_t*)&lp;
}

// ---------------------------------------------------------------------------
// Kernel 0a: fp32 input -> bf16 hi/lo split
// ---------------------------------------------------------------------------
__global__ __launch_bounds__(256) void convert_a_kernel(const float* __restrict__ in)
{
    int i = blockIdx.x * 256 + threadIdx.x;
    float4 v = ((const float4*)in)[i];
    __nv_bfloat16 h0 = __float2bfloat16(v.x), h1 = __float2bfloat16(v.y);
    __nv_bfloat16 h2 = __float2bfloat16(v.z), h3 = __float2bfloat16(v.w);
    __nv_bfloat16 l0 = __float2bfloat16(v.x - __bfloat162float(h0));
    __nv_bfloat16 l1 = __float2bfloat16(v.y - __bfloat162float(h1));
    __nv_bfloat16 l2 = __float2bfloat16(v.z - __bfloat162float(h2));
    __nv_bfloat16 l3 = __float2bfloat16(v.w - __bfloat162float(h3));
    uint2 hp, lp;
    hp.x = (uint32_t)__bfloat16_as_ushort(h0) | ((uint32_t)__bfloat16_as_ushort(h1) << 16);
    hp.y = (uint32_t)__bfloat16_as_ushort(h2) | ((uint32_t)__bfloat16_as_ushort(h3) << 16);
    lp.x = (uint32_t)__bfloat16_as_ushort(l0) | ((uint32_t)__bfloat16_as_ushort(l1) << 16);
    lp.y = (uint32_t)__bfloat16_as_ushort(l2) | ((uint32_t)__bfloat16_as_ushort(l3) << 16);
    ((uint2*)g_a_hi)[i] = hp;
    ((uint2*)g_a_lo)[i] = lp;
}

// ---------------------------------------------------------------------------
// Kernel 0b: W [1024,128] fp32 -> transposed bf16 hi/lo [128,1024]
// ---------------------------------------------------------------------------
__global__ __launch_bounds__(256) void convert_w_kernel(
    const float* __restrict__ Wq, const float* __restrict__ Wk,
    const float* __restrict__ Wv)
{
    int z = blockIdx.y;
    const float* W = (z == 0) ? Wq : (z == 1) ? Wk : Wv;
    int idx = blockIdx.x * 256 + threadIdx.x;
    int k = idx >> 7, n = idx & 127;
    float x = W[idx];
    __nv_bfloat16 h = __float2bfloat16(x);
    __nv_bfloat16 l = __float2bfloat16(x - __bfloat162float(h));
    size_t o = (size_t)(z * H_ + n) * D_ + k;
    g_wt_hi[o] = h;
    g_wt_lo[o] = l;
}

// ---------------------------------------------------------------------------
// Kernel 1: QKV projection, mma.sync bf16 3-term, 2-stage cp.async pipeline,
// term-major MMA ordering.  CTA: 128x128, 8 warps (32x64 warp tile), grid.z=z.
// ---------------------------------------------------------------------------
#define KST 144
#define QA_HI 0
#define QA_LO 18432
#define QW_HI 36864
#define QW_LO 55296
#define QSTG  73728
#define QKV_SMEM (2*QSTG)       // 147456

__global__ __launch_bounds__(256, 1) void qkv_gemm()
{
    extern __shared__ char smc[];
    const uint32_t sb = smem_u32(smc);
    const int tid = threadIdx.x, lane = tid & 31, wid = tid >> 5;
    const int wm = wid >> 1, wn = wid & 1;
    const int m0 = blockIdx.x * 128, z = blockIdx.z;
    const int g = lane >> 2, tg = lane & 3;

    const __nv_bfloat16* wt_h = g_wt_hi + (size_t)z * H_ * D_;
    const __nv_bfloat16* wt_l = g_wt_lo + (size_t)z * H_ * D_;

    float acc[2][8][4];
    #pragma unroll
    for (int a = 0; a < 2; a++)
        #pragma unroll
        for (int b = 0; b < 8; b++)
            #pragma unroll
            for (int c = 0; c < 4; c++) acc[a][b][c] = 0.f;

    // ---- issue lambda-ish macro: load chunk ch into stage st ----
    #define QKV_ISSUE(ch, st) do {                                            \
        const int k0_ = (ch) * 64;                                            \
        const uint32_t s0_ = sb + (st) * QSTG;                                \
        _Pragma("unroll")                                                     \
        for (int i = 0; i < 16; i++) {                                        \
            const int buf = i >> 2;                                           \
            const int rem = tid + (i & 3) * 256;                              \
            const int row = rem >> 3, c = rem & 7;                            \
            uint32_t d = s0_ + buf * 18432 + row * KST + c * 16;              \
            const __nv_bfloat16* src;                                         \
            if (buf == 0)      src = g_a_hi + (size_t)(m0 + row) * D_ + k0_ + c * 8; \
            else if (buf == 1) src = g_a_lo + (size_t)(m0 + row) * D_ + k0_ + c * 8; \
            else if (buf == 2) src = wt_h + (size_t)row * D_ + k0_ + c * 8;   \
            else               src = wt_l + (size_t)row * D_ + k0_ + c * 8;   \
        cp16(d, src);                                                         \
        }                                                                     \
    } while (0)

    QKV_ISSUE(0, 0); CP_COMMIT();

    for (int ch = 0; ch < 16; ch++) {
        if (ch < 15) { QKV_ISSUE(ch + 1, (ch + 1) & 1); CP_COMMIT(); CP_WAIT1(); }
        else CP_WAIT0();
        __syncthreads();

        const uint32_t s0 = sb + (ch & 1) * QSTG;
        #pragma unroll
        for (int s = 0; s < 4; s++) {
            uint32_t ah[2][4], al[2][4];
            #pragma unroll
            for (int mt = 0; mt < 2; mt++) {
                uint32_t ar = (uint32_t)((wm * 32 + mt * 16 + (lane & 15)) * KST
                               + (s * 16 + (lane >> 4) * 8) * 2);
                ldsm_x4(ah[mt], s0 + QA_HI + ar);
                ldsm_x4(al[mt], s0 + QA_LO + ar);
            }
            uint32_t bh[4][4], bl[4][4];
            #pragma unroll
            for (int p = 0; p < 4; p++) {
                uint32_t br = (uint32_t)((wn * 64 + p * 16 + (lane >> 4) * 8 + (lane & 7)) * KST
                               + (s * 16 + ((lane >> 3) & 1) * 8) * 2);
                ldsm_x4(bh[p], s0 + QW_HI + br);
                ldsm_x4(bl[p], s0 + QW_LO + br);
            }
            // term-major: 16 independent accumulators between chain reuse
            #pragma unroll
            for (int p = 0; p < 4; p++)
                #pragma unroll
                for (int mt = 0; mt < 2; mt++) {
                    mma16816(acc[mt][2*p],   ah[mt], bh[p]);
                    mma16816(acc[mt][2*p+1], ah[mt], bh[p] + 2);
                }
            #pragma unroll
            for (int p = 0; p < 4; p++)
                #pragma unroll
                for (int mt = 0; mt < 2; mt++) {
                    mma16816(acc[mt][2*p],   ah[mt], bl[p]);
                    mma16816(acc[mt][2*p+1], ah[mt], bl[p] + 2);
                }
            #pragma unroll
            for (int p = 0; p < 4; p++)
                #pragma unroll
                for (int mt = 0; mt < 2; mt++) {
                    mma16816(acc[mt][2*p],   al[mt], bh[p]);
                    mma16816(acc[mt][2*p+1], al[mt], bh[p] + 2);
                }
        }
        __syncthreads();
    }

    __nv_bfloat16 *oh, *ol;
    if (z == 0)      { oh = g_qh; ol = g_ql; }
    else if (z == 1) { oh = g_kh; ol = g_kl; }
    else             { oh = g_vh; ol = g_vl; }
    const float scl = (z == 0) ? 0.0883883476483184405f : 1.0f;

    #pragma unroll
    for (int mt = 0; mt < 2; mt++)
        #pragma unroll
        for (int nt = 0; nt < 8; nt++) {
            float c0 = acc[mt][nt][0] * scl, c1 = acc[mt][nt][1] * scl;
            float c2 = acc[mt][nt][2] * scl, c3 = acc[mt][nt][3] * scl;
            int r0  = m0 + wm * 32 + mt * 16 + g;
            int col = wn * 64 + nt * 8 + tg * 2;
            uint32_t h01, l01, h23, l23;
            split2(c0, c1, h01, l01);
            split2(c2, c3, h23, l23);
            *(uint32_t*)(oh + (size_t)r0 * H_ + col)       = h01;
            *(uint32_t*)(ol + (size_t)r0 * H_ + col)       = l01;
            *(uint32_t*)(oh + (size_t)(r0 + 8) * H_ + col) = h23;
            *(uint32_t*)(ol + (size_t)(r0 + 8) * H_ + col) = l23;
        }
}

// ---------------------------------------------------------------------------
// Kernel 2: causal flash attention.  CTA = 128 queries, 8 warps (16 rows/warp),
// key tiles of 64, Q persistent in smem, 2-stage K/V pipeline, term-major MMA.
// ---------------------------------------------------------------------------
#define QS 272
#define AQ_HI 0
#define AQ_LO 34816
#define AKV0  69632              // stage base; stage size:
#define ASTG  69632              // 4 bufs x 64 x 272
#define AK_HI 0
#define AK_LO 17408
#define AV_HI 34816
#define AV_LO 52224
#define ATT_SMEM (AKV0 + 2*ASTG) // 208896

__global__ __launch_bounds__(256, 1) void attn_mma(float* __restrict__ out)
{
    extern __shared__ char smc[];
    const uint32_t sb = smem_u32(smc);
    const int tid = threadIdx.x, lane = tid & 31, w = tid >> 5;
    const int b  = blockIdx.y;
    const int it = 15 - blockIdx.x;          // heavy tiles first
    const int q0 = it * 128;
    const int jmax = 2 * it + 1;
    const int g = lane >> 2, tg = lane & 3;
    const size_t base = (size_t)b * S_ * H_;

    #define ATT_ISSUE_KV(j, st) do {                                          \
        const int t0_ = (j) * 64;                                             \
        const uint32_t s0_ = sb + AKV0 + (st) * ASTG;                         \
        _Pragma("unroll")                                                     \
        for (int i = 0; i < 16; i++) {                                        \
            const int buf = i >> 2;                                           \
            const int rem = tid + (i & 3) * 256;                              \
            const int row = rem >> 4, c = rem & 15;                           \
            uint32_t d = s0_ + buf * 17408 + row * QS + c * 16;               \
            const __nv_bfloat16* src;                                         \
            if (buf == 0)      src = g_kh + base + (size_t)(t0_ + row) * H_ + c * 8; \
            else if (buf == 1) src = g_kl + base + (size_t)(t0_ + row) * H_ + c * 8; \
            else if (buf == 2) src = g_vh + base + (size_t)(t0_ + row) * H_ + c * 8; \
            else               src = g_vl + base + (size_t)(t0_ + row) * H_ + c * 8; \
            cp16(d, src);                                                     \
        }                                                                     \
    } while (0)

    // ---- issue Q (group), KV tile 0 (group) ----
    #pragma unroll
    for (int i = 0; i < 16; i++) {
        const int buf = i >> 3;
        const int rem = tid + (i & 7) * 256;
        const int row = rem >> 4, c = rem & 15;
        uint32_t d = sb + buf * 34816 + row * QS + c * 16;
        const __nv_bfloat16* src = (buf == 0 ? g_qh : g_ql) + base
                                   + (size_t)(q0 + row) * H_ + c * 8;
        cp16(d, src);
    }
    CP_COMMIT();
    ATT_ISSUE_KV(0, 0); CP_COMMIT();
    CP_WAIT1();                     // Q ready
    __syncthreads();

    float o[16][4];
    #pragma unroll
    for (int f = 0; f < 16; f++)
        #pragma unroll
        for (int c = 0; c < 4; c++) o[f][c] = 0.f;
    float m0r = -INFINITY, m1r = -INFINITY, l0 = 0.f, l1 = 0.f;

    for (int j = 0; j <= jmax; j++) {
        if (j < jmax) { ATT_ISSUE_KV(j + 1, (j + 1) & 1); CP_COMMIT(); CP_WAIT1(); }
        else CP_WAIT0();
        __syncthreads();

        const int t0 = j * 64;
        const uint32_t stb = sb + AKV0 + (j & 1) * ASTG;

        if (t0 <= q0 + w * 16 + 15) {      // warp has at least one unmasked row
            // ---- S = Q K^T (term-major) ----
            float s[8][4];
            #pragma unroll
            for (int nt = 0; nt < 8; nt++)
                #pragma unroll
                for (int c = 0; c < 4; c++) s[nt][c] = 0.f;

            #pragma unroll
            for (int ks = 0; ks < 8; ks++) {
                uint32_t qh[4], ql[4];
                uint32_t ar = (uint32_t)((w * 16 + (lane & 15)) * QS
                               + (ks * 16 + (lane >> 4) * 8) * 2);
                ldsm_x4(qh, sb + AQ_HI + ar);
                ldsm_x4(ql, sb + AQ_LO + ar);
                uint32_t bh[4][4], bl[4][4];
                #pragma unroll
                for (int p = 0; p < 4; p++) {
                    uint32_t br = (uint32_t)((p * 16 + (lane >> 4) * 8 + (lane & 7)) * QS
                                   + (ks * 16 + ((lane >> 3) & 1) * 8) * 2);
                    ldsm_x4(bh[p], stb + AK_HI + br);
                    ldsm_x4(bl[p], stb + AK_LO + br);
                }
                #pragma unroll
                for (int p = 0; p < 4; p++) {
                    mma16816(s[2*p],   qh, bh[p]);
                    mma16816(s[2*p+1], qh, bh[p] + 2);
                }
                #pragma unroll
                for (int p = 0; p < 4; p++) {
                    mma16816(s[2*p],   qh, bl[p]);
                    mma16816(s[2*p+1], qh, bl[p] + 2);
                }
                #pragma unroll
                for (int p = 0; p < 4; p++) {
                    mma16816(s[2*p],   ql, bh[p]);
                    mma16816(s[2*p+1], ql, bh[p] + 2);
                }
            }

            // ---- causal mask (only near diagonal) ----
            if (j >= jmax - 1) {
                int r0 = q0 + w * 16 + g, r1 = r0 + 8;
                #pragma unroll
                for (int nt = 0; nt < 8; nt++) {
                    int kc = t0 + nt * 8 + tg * 2;
                    if (kc     > r0) s[nt][0] = -INFINITY;
                    if (kc + 1 > r0) s[nt][1] = -INFINITY;
                    if (kc     > r1) s[nt][2] = -INFINITY;
                    if (kc + 1 > r1) s[nt][3] = -INFINITY;
                }
            }

            // ---- online softmax ----
            float ml0 = -INFINITY, ml1 = -INFINITY;
            #pragma unroll
            for (int nt = 0; nt < 8; nt++) {
                ml0 = fmaxf(ml0, fmaxf(s[nt][0], s[nt][1]));
                ml1 = fmaxf(ml1, fmaxf(s[nt][2], s[nt][3]));
            }
            #pragma unroll
            for (int ofs = 1; ofs <= 2; ofs <<= 1) {
                ml0 = fmaxf(ml0, __shfl_xor_sync(0xffffffffu, ml0, ofs));
                ml1 = fmaxf(ml1, __shfl_xor_sync(0xffffffffu, ml1, ofs));
            }
            float mn0 = fmaxf(m0r, ml0), mn1 = fmaxf(m1r, ml1);
            float a0 = __expf(m0r - mn0), a1 = __expf(m1r - mn1);
            m0r = mn0; m1r = mn1;

            float rs0 = 0.f, rs1 = 0.f;
            #pragma unroll
            for (int nt = 0; nt < 8; nt++) {
                s[nt][0] = __expf(s[nt][0] - mn0); rs0 += s[nt][0];
                s[nt][1] = __expf(s[nt][1] - mn0); rs0 += s[nt][1];
                s[nt][2] = __expf(s[nt][2] - mn1); rs1 += s[nt][2];
                s[nt][3] = __expf(s[nt][3] - mn1); rs1 += s[nt][3];
            }
            #pragma unroll
            for (int ofs = 1; ofs <= 2; ofs <<= 1) {
                rs0 += __shfl_xor_sync(0xffffffffu, rs0, ofs);
                rs1 += __shfl_xor_sync(0xffffffffu, rs1, ofs);
            }
            l0 = l0 * a0 + rs0;
            l1 = l1 * a1 + rs1;
            #pragma unroll
            for (int f = 0; f < 16; f++) {
                o[f][0] *= a0; o[f][1] *= a0;
                o[f][2] *= a1; o[f][3] *= a1;
            }

            // ---- pack P ----
            uint32_t ph[4][4], pl[4][4];
            #pragma unroll
            for (int s4 = 0; s4 < 4; s4++) {
                split2(s[2*s4][0],   s[2*s4][1],   ph[s4][0], pl[s4][0]);
                split2(s[2*s4][2],   s[2*s4][3],   ph[s4][1], pl[s4][1]);
                split2(s[2*s4+1][0], s[2*s4+1][1], ph[s4][2], pl[s4][2]);
                split2(s[2*s4+1][2], s[2*s4+1][3], ph[s4][3], pl[s4][3]);
            }

            // ---- O += P V (term-major, half-N groups) ----
            #pragma unroll
            for (int s4 = 0; s4 < 4; s4++) {
                #pragma unroll
                for (int half = 0; half < 2; half++) {
                    uint32_t vh[4][4], vl[4][4];
                    #pragma unroll
                    for (int p4 = 0; p4 < 4; p4++) {
                        int p = half * 4 + p4;
                        uint32_t vr = (uint32_t)((s4 * 16 + (lane & 7) + ((lane >> 3) & 1) * 8) * QS
                                       + (p * 2 + (lane >> 4)) * 16);
                        ldsm_x4_t(vh[p4], stb + AV_HI + vr);
                        ldsm_x4_t(vl[p4], stb + AV_LO + vr);
                    }
                    #pragma unroll
                    for (int p4 = 0; p4 < 4; p4++) {
                        int p = half * 4 + p4;
                        mma16816(o[2*p],   ph[s4], vh[p4]);
                        mma16816(o[2*p+1], ph[s4], vh[p4] + 2);
                    }
                    #pragma unroll
                    for (int p4 = 0; p4 < 4; p4++) {
                        int p = half * 4 + p4;
                        mma16816(o[2*p],   ph[s4], vl[p4]);
                        mma16816(o[2*p+1], ph[s4], vl[p4] + 2);
                    }
                    #pragma unroll
                    for (int p4 = 0; p4 < 4; p4++) {
                        int p = half * 4 + p4;
                        mma16816(o[2*p],   pl[s4], vh[p4]);
                        mma16816(o[2*p+1], pl[s4], vh[p4] + 2);
                    }
                }
            }
        }
        __syncthreads();
    }

    // ---- normalize + store ----
    float i0 = 1.f / l0, i1 = 1.f / l1;
    int r0 = q0 + w * 16 + g;
    #pragma unroll
    for (int f = 0; f < 16; f++) {
        float2 v0 = make_float2(o[f][0] * i0, o[f][1] * i0);
        float2 v1 = make_float2(o[f][2] * i1, o[f][3] * i1);
        *(float2*)(out + base + (size_t)r0 * H_ + f * 8 + tg * 2)       = v0;
        *(float2*)(out + base + (size_t)(r0 + 8) * H_ + f * 8 + tg * 2) = v1;
    }
}

// ---------------------------------------------------------------------------
extern "C" void kernel_launch(void* const* d_in, const int* in_sizes, int n_in,
                              void* d_out, int out_size)
{
    const float* input = (const float*)d_in[0];
    const float* Wq    = (const float*)d_in[1];
    const float* Wk    = (const float*)d_in[2];
    const float* Wv    = (const float*)d_in[3];
    float* out = (float*)d_out;

    cudaFuncSetAttribute(qkv_gemm, cudaFuncAttributeMaxDynamicSharedMemorySize, QKV_SMEM);
    cudaFuncSetAttribute(attn_mma, cudaFuncAttributeMaxDynamicSharedMemorySize, ATT_SMEM);

    convert_a_kernel<<<(M_TOT * D_ / 4) / 256, 256>>>(input);
    convert_w_kernel<<<dim3(512, 3), 256>>>(Wq, Wk, Wv);
    qkv_gemm<<<dim3(M_TOT / 128, 1, 3), 256, QKV_SMEM>>>();
    attn_mma<<<dim3(16, B_), 256, ATT_SMEM>>>(out);
}

// round 6
// speedup vs baseline: 1.1212x; 1.1212x over previous
#include <cuda_runtime.h>
#include <cuda_bf16.h>
#include <cstdint>

#define B_ 16
#define S_ 2048
#define D_ 1024
#define H_ 128
#define M_TOT (B_*S_)

// ---------------- scratch (__device__ globals; allocation-free rule) -------
__device__ __nv_bfloat16 g_wt_hi[3 * H_ * D_];   // [z][n][k] (W transposed)
__device__ __nv_bfloat16 g_wt_lo[3 * H_ * D_];
__device__ __nv_bfloat16 g_qh[M_TOT * H_], g_ql[M_TOT * H_];
__device__ __nv_bfloat16 g_kh[M_TOT * H_], g_kl[M_TOT * H_];
__device__ __nv_bfloat16 g_vh[M_TOT * H_], g_vl[M_TOT * H_];

// ---------------- helpers (sm_80-baseline, family-target safe) -------------
__device__ __forceinline__ uint32_t smem_u32(const void* p) {
    uint32_t a;
    asm("{ .reg .u64 t; cvta.to.shared.u64 t, %1; cvt.u32.u64 %0, t; }"
        : "=r"(a) : "l"(p));
    return a;
}
__device__ __forceinline__ void cp16(uint32_t dst, const void* src) {
    asm volatile("cp.async.cg.shared.global [%0], [%1], 16;" :: "r"(dst), "l"(src));
}
#define CP_COMMIT() asm volatile("cp.async.commit_group;" ::: "memory")
#define CP_WAIT0()  asm volatile("cp.async.wait_group 0;" ::: "memory")
#define CP_WAIT1()  asm volatile("cp.async.wait_group 1;" ::: "memory")

__device__ __forceinline__ void ldsm_x4(uint32_t r[4], uint32_t addr) {
    asm volatile("ldmatrix.sync.aligned.m8n8.x4.shared.b16 {%0,%1,%2,%3}, [%4];"
        : "=r"(r[0]), "=r"(r[1]), "=r"(r[2]), "=r"(r[3]) : "r"(addr));
}
__device__ __forceinline__ void ldsm_x4_t(uint32_t r[4], uint32_t addr) {
    asm volatile("ldmatrix.sync.aligned.m8n8.x4.trans.shared.b16 {%0,%1,%2,%3}, [%4];"
        : "=r"(r[0]), "=r"(r[1]), "=r"(r[2]), "=r"(r[3]) : "r"(addr));
}
__device__ __forceinline__ void mma16816(float c[4], const uint32_t a[4],
                                         const uint32_t b[2]) {
    asm volatile("mma.sync.aligned.m16n8k16.row.col.f32.bf16.bf16.f32 "
        "{%0,%1,%2,%3}, {%4,%5,%6,%7}, {%8,%9}, {%0,%1,%2,%3};"
        : "+f"(c[0]), "+f"(c[1]), "+f"(c[2]), "+f"(c[3])
        : "r"(a[0]), "r"(a[1]), "r"(a[2]), "r"(a[3]), "r"(b[0]), "r"(b[1]));
}
__device__ __forceinline__ void split2(float x0, float x1, uint32_t& h, uint32_t& l) {
    __nv_bfloat16 h0 = __float2bfloat16(x0), h1 = __float2bfloat16(x1);
    __nv_bfloat162 hp = __halves2bfloat162(h0, h1);
    h = *(uint32_t*)&hp;
    __nv_bfloat16 l0 = __float2bfloat16(x0 - __bfloat162float(h0));
    __nv_bfloat16 l1 = __float2bfloat16(x1 - __bfloat162float(h1));
    __nv_bfloat162 lp = __halves2bfloat162(l0, l1);
    l = *(uint32_t*)&lp;
}
__device__ __forceinline__ float ex2f(float x) {
    float y;
    asm("ex2.approx.f32 %0, %1;" : "=f"(y) : "f"(x));
    return y;
}

// ---------------------------------------------------------------------------
// Kernel 0: W [1024,128] fp32 -> transposed bf16 hi/lo [128,1024]
// ---------------------------------------------------------------------------
__global__ __launch_bounds__(256) void convert_w_kernel(
    const float* __restrict__ Wq, const float* __restrict__ Wk,
    const float* __restrict__ Wv)
{
    int z = blockIdx.y;
    const float* W = (z == 0) ? Wq : (z == 1) ? Wk : Wv;
    int idx = blockIdx.x * 256 + threadIdx.x;
    int k = idx >> 7, n = idx & 127;
    float x = W[idx];
    __nv_bfloat16 h = __float2bfloat16(x);
    __nv_bfloat16 l = __float2bfloat16(x - __bfloat162float(h));
    size_t o = (size_t)(z * H_ + n) * D_ + k;
    g_wt_hi[o] = h;
    g_wt_lo[o] = l;
}

// ---------------------------------------------------------------------------
// Kernel 1: QKV projection, mma.sync bf16 3-term, A loaded as fp32 and split
// in-register (convert kernel fused away). Grid interleave (m*3+z) for L2
// A-reuse across z. 2 CTAs/SM, single-stage smem.
// ---------------------------------------------------------------------------
#define KST 144
#define QA_HI 0
#define QA_LO 18432
#define QW_HI 36864
#define QW_LO 55296
#define QKV_SMEM 73728

__global__ __launch_bounds__(256, 2) void qkv_gemm(const float* __restrict__ A)
{
    extern __shared__ char smc[];
    const uint32_t sb = smem_u32(smc);
    const int tid = threadIdx.x, lane = tid & 31, wid = tid >> 5;
    const int wm = wid >> 1, wn = wid & 1;
    const int m0 = (blockIdx.x / 3) * 128, z = blockIdx.x % 3;
    const int g = lane >> 2, tg = lane & 3;

    const __nv_bfloat16* wt_h = g_wt_hi + (size_t)z * H_ * D_;
    const __nv_bfloat16* wt_l = g_wt_lo + (size_t)z * H_ * D_;

    float acc[2][8][4];
    #pragma unroll
    for (int a = 0; a < 2; a++)
        #pragma unroll
        for (int b = 0; b < 8; b++)
            #pragma unroll
            for (int c = 0; c < 4; c++) acc[a][b][c] = 0.f;

    for (int ch = 0; ch < 16; ch++) {
        const int k0 = ch * 64;
        // W hi/lo via cp.async
        #pragma unroll
        for (int i = 0; i < 8; i++) {
            const int buf = i >> 2;
            const int rem = tid + (i & 3) * 256;
            const int row = rem >> 3, c = rem & 7;
            uint32_t d = sb + QW_HI + buf * 18432 + row * KST + c * 16;
            const __nv_bfloat16* src = (buf == 0 ? wt_h : wt_l)
                                       + (size_t)row * D_ + k0 + c * 8;
            cp16(d, src);
        }
        CP_COMMIT();

        // A fp32 LDG -> in-register split -> STS (hi/lo)
        #pragma unroll
        for (int gi = 0; gi < 4; gi++) {
            const int u = tid + gi * 256;          // 0..1023 (128 rows x 8 groups)
            const int row = u >> 3, c8 = u & 7;
            const float* ap = A + (size_t)(m0 + row) * D_ + k0 + c8 * 8;
            float4 f0 = *(const float4*)ap;
            float4 f1 = *(const float4*)(ap + 4);
            uint32_t h0, l0, h1, l1, h2, l2, h3, l3;
            split2(f0.x, f0.y, h0, l0);
            split2(f0.z, f0.w, h1, l1);
            split2(f1.x, f1.y, h2, l2);
            split2(f1.z, f1.w, h3, l3);
            uint4 hv = make_uint4(h0, h1, h2, h3);
            uint4 lv = make_uint4(l0, l1, l2, l3);
            *(uint4*)(smc + QA_HI + row * KST + c8 * 16) = hv;
            *(uint4*)(smc + QA_LO + row * KST + c8 * 16) = lv;
        }
        CP_WAIT0();
        __syncthreads();

        #pragma unroll
        for (int s = 0; s < 4; s++) {
            uint32_t ah[2][4], al[2][4];
            #pragma unroll
            for (int mt = 0; mt < 2; mt++) {
                uint32_t ar = (uint32_t)((wm * 32 + mt * 16 + (lane & 15)) * KST
                               + (s * 16 + (lane >> 4) * 8) * 2);
                ldsm_x4(ah[mt], sb + QA_HI + ar);
                ldsm_x4(al[mt], sb + QA_LO + ar);
            }
            uint32_t bh[4][4], bl[4][4];
            #pragma unroll
            for (int p = 0; p < 4; p++) {
                uint32_t br = (uint32_t)((wn * 64 + p * 16 + (lane >> 4) * 8 + (lane & 7)) * KST
                               + (s * 16 + ((lane >> 3) & 1) * 8) * 2);
                ldsm_x4(bh[p], sb + QW_HI + br);
                ldsm_x4(bl[p], sb + QW_LO + br);
            }
            #pragma unroll
            for (int p = 0; p < 4; p++)
                #pragma unroll
                for (int mt = 0; mt < 2; mt++) {
                    mma16816(acc[mt][2*p],   ah[mt], bh[p]);
                    mma16816(acc[mt][2*p+1], ah[mt], bh[p] + 2);
                }
            #pragma unroll
            for (int p = 0; p < 4; p++)
                #pragma unroll
                for (int mt = 0; mt < 2; mt++) {
                    mma16816(acc[mt][2*p],   ah[mt], bl[p]);
                    mma16816(acc[mt][2*p+1], ah[mt], bl[p] + 2);
                }
            #pragma unroll
            for (int p = 0; p < 4; p++)
                #pragma unroll
                for (int mt = 0; mt < 2; mt++) {
                    mma16816(acc[mt][2*p],   al[mt], bh[p]);
                    mma16816(acc[mt][2*p+1], al[mt], bh[p] + 2);
                }
        }
        __syncthreads();
    }

    __nv_bfloat16 *oh, *ol;
    if (z == 0)      { oh = g_qh; ol = g_ql; }
    else if (z == 1) { oh = g_kh; ol = g_kl; }
    else             { oh = g_vh; ol = g_vl; }
    // Q gets 1/sqrt(H) * log2(e) folded in (softmax runs in exp2 domain)
    const float scl = (z == 0)
        ? (0.0883883476483184405f * 1.4426950408889634f) : 1.0f;

    #pragma unroll
    for (int mt = 0; mt < 2; mt++)
        #pragma unroll
        for (int nt = 0; nt < 8; nt++) {
            float c0 = acc[mt][nt][0] * scl, c1 = acc[mt][nt][1] * scl;
            float c2 = acc[mt][nt][2] * scl, c3 = acc[mt][nt][3] * scl;
            int r0  = m0 + wm * 32 + mt * 16 + g;
            int col = wn * 64 + nt * 8 + tg * 2;
            uint32_t h01, l01, h23, l23;
            split2(c0, c1, h01, l01);
            split2(c2, c3, h23, l23);
            *(uint32_t*)(oh + (size_t)r0 * H_ + col)       = h01;
            *(uint32_t*)(ol + (size_t)r0 * H_ + col)       = l01;
            *(uint32_t*)(oh + (size_t)(r0 + 8) * H_ + col) = h23;
            *(uint32_t*)(ol + (size_t)(r0 + 8) * H_ + col) = l23;
        }
}

// ---------------------------------------------------------------------------
// Kernel 2: causal flash attention.  CTA = 128 queries, 8 warps (16 rows/warp),
// key tiles of 64, Q fragments in registers, 2-stage K/V pipeline, exp2
// softmax, deferred row-sum reduction.
// ---------------------------------------------------------------------------
#define QS 272
#define ASTG  69632              // 4 bufs x 64 x 272
#define AK_HI 0
#define AK_LO 17408
#define AV_HI 34816
#define AV_LO 52224
#define ATT_SMEM (2*ASTG)        // 139264

__global__ __launch_bounds__(256, 1) void attn_mma(float* __restrict__ out)
{
    extern __shared__ char smc[];
    const uint32_t sb = smem_u32(smc);
    const int tid = threadIdx.x, lane = tid & 31, w = tid >> 5;
    const int b  = blockIdx.y;
    const int it = 15 - blockIdx.x;          // heavy tiles first
    const int q0 = it * 128;
    const int jmax = 2 * it + 1;
    const int g = lane >> 2, tg = lane & 3;
    const size_t base = (size_t)b * S_ * H_;

    #define ATT_ISSUE_KV(j, st) do {                                          \
        const int t0_ = (j) * 64;                                             \
        const uint32_t s0_ = sb + (st) * ASTG;                                \
        _Pragma("unroll")                                                     \
        for (int i = 0; i < 16; i++) {                                        \
            const int buf = i >> 2;                                           \
            const int rem = tid + (i & 3) * 256;                              \
            const int row = rem >> 4, c = rem & 15;                           \
            uint32_t d = s0_ + buf * 17408 + row * QS + c * 16;               \
            const __nv_bfloat16* src;                                         \
            if (buf == 0)      src = g_kh + base + (size_t)(t0_ + row) * H_ + c * 8; \
            else if (buf == 1) src = g_kl + base + (size_t)(t0_ + row) * H_ + c * 8; \
            else if (buf == 2) src = g_vh + base + (size_t)(t0_ + row) * H_ + c * 8; \
            else               src = g_vl + base + (size_t)(t0_ + row) * H_ + c * 8; \
            cp16(d, src);                                                     \
        }                                                                     \
    } while (0)

    // ---- stage Q (into stage-0 area), capture fragments in registers ----
    #pragma unroll
    for (int i = 0; i < 16; i++) {
        const int buf = i >> 3;
        const int rem = tid + (i & 7) * 256;
        const int row = rem >> 4, c = rem & 15;
        uint32_t d = sb + buf * 34816 + row * QS + c * 16;
        const __nv_bfloat16* src = (buf == 0 ? g_qh : g_ql) + base
                                   + (size_t)(q0 + row) * H_ + c * 8;
        cp16(d, src);
    }
    CP_COMMIT(); CP_WAIT0();
    __syncthreads();
    uint32_t qh[8][4], ql[8][4];
    #pragma unroll
    for (int ks = 0; ks < 8; ks++) {
        uint32_t ar = (uint32_t)((w * 16 + (lane & 15)) * QS
                       + (ks * 16 + (lane >> 4) * 8) * 2);
        ldsm_x4(qh[ks], sb + ar);
        ldsm_x4(ql[ks], sb + 34816 + ar);
    }
    __syncthreads();                       // Q staging dead; stage 0 reusable

    ATT_ISSUE_KV(0, 0); CP_COMMIT();

    float o[16][4];
    #pragma unroll
    for (int f = 0; f < 16; f++)
        #pragma unroll
        for (int c = 0; c < 4; c++) o[f][c] = 0.f;
    float m0r = -INFINITY, m1r = -INFINITY, l0 = 0.f, l1 = 0.f;

    for (int j = 0; j <= jmax; j++) {
        if (j < jmax) { ATT_ISSUE_KV(j + 1, (j + 1) & 1); CP_COMMIT(); CP_WAIT1(); }
        else CP_WAIT0();
        __syncthreads();

        const int t0 = j * 64;
        const uint32_t stb = sb + (j & 1) * ASTG;

        if (t0 <= q0 + w * 16 + 15) {      // warp has at least one unmasked row
            // ---- S = Q K^T (term-major; Q from registers) ----
            float s[8][4];
            #pragma unroll
            for (int nt = 0; nt < 8; nt++)
                #pragma unroll
                for (int c = 0; c < 4; c++) s[nt][c] = 0.f;

            #pragma unroll
            for (int ks = 0; ks < 8; ks++) {
                uint32_t bh[4][4], bl[4][4];
                #pragma unroll
                for (int p = 0; p < 4; p++) {
                    uint32_t br = (uint32_t)((p * 16 + (lane >> 4) * 8 + (lane & 7)) * QS
                                   + (ks * 16 + ((lane >> 3) & 1) * 8) * 2);
                    ldsm_x4(bh[p], stb + AK_HI + br);
                    ldsm_x4(bl[p], stb + AK_LO + br);
                }
                #pragma unroll
                for (int p = 0; p < 4; p++) {
                    mma16816(s[2*p],   qh[ks], bh[p]);
                    mma16816(s[2*p+1], qh[ks], bh[p] + 2);
                }
                #pragma unroll
                for (int p = 0; p < 4; p++) {
                    mma16816(s[2*p],   qh[ks], bl[p]);
                    mma16816(s[2*p+1], qh[ks], bl[p] + 2);
                }
                #pragma unroll
                for (int p = 0; p < 4; p++) {
                    mma16816(s[2*p],   ql[ks], bh[p]);
                    mma16816(s[2*p+1], ql[ks], bh[p] + 2);
                }
            }

            // ---- causal mask (only near diagonal) ----
            if (j >= jmax - 1) {
                int r0 = q0 + w * 16 + g, r1 = r0 + 8;
                #pragma unroll
                for (int nt = 0; nt < 8; nt++) {
                    int kc = t0 + nt * 8 + tg * 2;
                    if (kc     > r0) s[nt][0] = -INFINITY;
                    if (kc + 1 > r0) s[nt][1] = -INFINITY;
                    if (kc     > r1) s[nt][2] = -INFINITY;
                    if (kc + 1 > r1) s[nt][3] = -INFINITY;
                }
            }

            // ---- online softmax, exp2 domain ----
            float ml0 = -INFINITY, ml1 = -INFINITY;
            #pragma unroll
            for (int nt = 0; nt < 8; nt++) {
                ml0 = fmaxf(ml0, fmaxf(s[nt][0], s[nt][1]));
                ml1 = fmaxf(ml1, fmaxf(s[nt][2], s[nt][3]));
            }
            #pragma unroll
            for (int ofs = 1; ofs <= 2; ofs <<= 1) {
                ml0 = fmaxf(ml0, __shfl_xor_sync(0xffffffffu, ml0, ofs));
                ml1 = fmaxf(ml1, __shfl_xor_sync(0xffffffffu, ml1, ofs));
            }
            float mn0 = fmaxf(m0r, ml0), mn1 = fmaxf(m1r, ml1);
            float a0 = ex2f(m0r - mn0), a1 = ex2f(m1r - mn1);
            m0r = mn0; m1r = mn1;

            float rs0 = 0.f, rs1 = 0.f;
            #pragma unroll
            for (int nt = 0; nt < 8; nt++) {
                s[nt][0] = ex2f(s[nt][0] - mn0); rs0 += s[nt][0];
                s[nt][1] = ex2f(s[nt][1] - mn0); rs0 += s[nt][1];
                s[nt][2] = ex2f(s[nt][2] - mn1); rs1 += s[nt][2];
                s[nt][3] = ex2f(s[nt][3] - mn1); rs1 += s[nt][3];
            }
            // deferred cross-lane reduction: keep per-lane partials
            l0 = l0 * a0 + rs0;
            l1 = l1 * a1 + rs1;
            #pragma unroll
            for (int f = 0; f < 16; f++) {
                o[f][0] *= a0; o[f][1] *= a0;
                o[f][2] *= a1; o[f][3] *= a1;
            }

            // ---- pack P ----
            uint32_t ph[4][4], pl[4][4];
            #pragma unroll
            for (int s4 = 0; s4 < 4; s4++) {
                split2(s[2*s4][0],   s[2*s4][1],   ph[s4][0], pl[s4][0]);
                split2(s[2*s4][2],   s[2*s4][3],   ph[s4][1], pl[s4][1]);
                split2(s[2*s4+1][0], s[2*s4+1][1], ph[s4][2], pl[s4][2]);
                split2(s[2*s4+1][2], s[2*s4+1][3], ph[s4][3], pl[s4][3]);
            }

            // ---- O += P V (term-major, half-N groups) ----
            #pragma unroll
            for (int s4 = 0; s4 < 4; s4++) {
                #pragma unroll
                for (int half = 0; half < 2; half++) {
                    uint32_t vh[4][4], vl[4][4];
                    #pragma unroll
                    for (int p4 = 0; p4 < 4; p4++) {
                        int p = half * 4 + p4;
                        uint32_t vr = (uint32_t)((s4 * 16 + (lane & 7) + ((lane >> 3) & 1) * 8) * QS
                                       + (p * 2 + (lane >> 4)) * 16);
                        ldsm_x4_t(vh[p4], stb + AV_HI + vr);
                        ldsm_x4_t(vl[p4], stb + AV_LO + vr);
                    }
                    #pragma unroll
                    for (int p4 = 0; p4 < 4; p4++) {
                        int p = half * 4 + p4;
                        mma16816(o[2*p],   ph[s4], vh[p4]);
                        mma16816(o[2*p+1], ph[s4], vh[p4] + 2);
                    }
                    #pragma unroll
                    for (int p4 = 0; p4 < 4; p4++) {
                        int p = half * 4 + p4;
                        mma16816(o[2*p],   ph[s4], vl[p4]);
                        mma16816(o[2*p+1], ph[s4], vl[p4] + 2);
                    }
                    #pragma unroll
                    for (int p4 = 0; p4 < 4; p4++) {
                        int p = half * 4 + p4;
                        mma16816(o[2*p],   pl[s4], vh[p4]);
                        mma16816(o[2*p+1], pl[s4], vh[p4] + 2);
                    }
                }
            }
        }
        __syncthreads();
    }

    // ---- final cross-lane sum reduction, normalize + store ----
    #pragma unroll
    for (int ofs = 1; ofs <= 2; ofs <<= 1) {
        l0 += __shfl_xor_sync(0xffffffffu, l0, ofs);
        l1 += __shfl_xor_sync(0xffffffffu, l1, ofs);
    }
    float i0 = 1.f / l0, i1 = 1.f / l1;
    int r0 = q0 + w * 16 + g;
    #pragma unroll
    for (int f = 0; f < 16; f++) {
        float2 v0 = make_float2(o[f][0] * i0, o[f][1] * i0);
        float2 v1 = make_float2(o[f][2] * i1, o[f][3] * i1);
        *(float2*)(out + base + (size_t)r0 * H_ + f * 8 + tg * 2)       = v0;
        *(float2*)(out + base + (size_t)(r0 + 8) * H_ + f * 8 + tg * 2) = v1;
    }
}

// ---------------------------------------------------------------------------
extern "C" void kernel_launch(void* const* d_in, const int* in_sizes, int n_in,
                              void* d_out, int out_size)
{
    const float* input = (const float*)d_in[0];
    const float* Wq    = (const float*)d_in[1];
    const float* Wk    = (const float*)d_in[2];
    const float* Wv    = (const float*)d_in[3];
    float* out = (float*)d_out;

    cudaFuncSetAttribute(qkv_gemm, cudaFuncAttributeMaxDynamicSharedMemorySize, QKV_SMEM);
    cudaFuncSetAttribute(attn_mma, cudaFuncAttributeMaxDynamicSharedMemorySize, ATT_SMEM);

    convert_w_kernel<<<dim3(512, 3), 256>>>(Wq, Wk, Wv);
    qkv_gemm<<<dim3(3 * M_TOT / 128, 1, 1), 256, QKV_SMEM>>>(input);
    attn_mma<<<dim3(16, B_), 256, ATT_SMEM>>>(out);
}

// round 7
// speedup vs baseline: 1.6518x; 1.4732x over previous
#include <cuda_runtime.h>
#include <cuda_fp16.h>
#include <cstdint>

#define B_ 16
#define S_ 2048
#define D_ 1024
#define H_ 128
#define M_TOT (B_*S_)

// ---------------- scratch (__device__ globals; allocation-free rule) -------
__device__ __half g_wt[3 * H_ * D_];             // W single fp16, [z][n][k]
__device__ __half g_qh[M_TOT * H_], g_ql[M_TOT * H_];   // Q 2-term
__device__ __half g_k[M_TOT * H_];               // K single
__device__ __half g_v[M_TOT * H_];               // V single

// ---------------- helpers (sm_80-baseline, family-target safe) -------------
__device__ __forceinline__ uint32_t smem_u32(const void* p) {
    uint32_t a;
    asm("{ .reg .u64 t; cvta.to.shared.u64 t, %1; cvt.u32.u64 %0, t; }"
        : "=r"(a) : "l"(p));
    return a;
}
__device__ __forceinline__ void cp16(uint32_t dst, const void* src) {
    asm volatile("cp.async.cg.shared.global [%0], [%1], 16;" :: "r"(dst), "l"(src));
}
#define CP_COMMIT() asm volatile("cp.async.commit_group;" ::: "memory")
#define CP_WAIT0()  asm volatile("cp.async.wait_group 0;" ::: "memory")
#define CP_WAIT1()  asm volatile("cp.async.wait_group 1;" ::: "memory")

__device__ __forceinline__ void ldsm_x4(uint32_t r[4], uint32_t addr) {
    asm volatile("ldmatrix.sync.aligned.m8n8.x4.shared.b16 {%0,%1,%2,%3}, [%4];"
        : "=r"(r[0]), "=r"(r[1]), "=r"(r[2]), "=r"(r[3]) : "r"(addr));
}
__device__ __forceinline__ void ldsm_x4_t(uint32_t r[4], uint32_t addr) {
    asm volatile("ldmatrix.sync.aligned.m8n8.x4.trans.shared.b16 {%0,%1,%2,%3}, [%4];"
        : "=r"(r[0]), "=r"(r[1]), "=r"(r[2]), "=r"(r[3]) : "r"(addr));
}
__device__ __forceinline__ void mma16816(float c[4], const uint32_t a[4],
                                         const uint32_t b[2]) {
    asm volatile("mma.sync.aligned.m16n8k16.row.col.f32.f16.f16.f32 "
        "{%0,%1,%2,%3}, {%4,%5,%6,%7}, {%8,%9}, {%0,%1,%2,%3};"
        : "+f"(c[0]), "+f"(c[1]), "+f"(c[2]), "+f"(c[3])
        : "r"(a[0]), "r"(a[1]), "r"(a[2]), "r"(a[3]), "r"(b[0]), "r"(b[1]));
}
__device__ __forceinline__ void split2h(float x0, float x1, uint32_t& h, uint32_t& l) {
    __half h0 = __float2half_rn(x0), h1 = __float2half_rn(x1);
    __half2 hp = __halves2half2(h0, h1);
    h = *(uint32_t*)&hp;
    __half l0 = __float2half_rn(x0 - __half2float(h0));
    __half l1 = __float2half_rn(x1 - __half2float(h1));
    __half2 lp = __halves2half2(l0, l1);
    l = *(uint32_t*)&lp;
}
__device__ __forceinline__ uint32_t pack2h(float x0, float x1) {
    __half2 p = __floats2half2_rn(x0, x1);
    return *(uint32_t*)&p;
}
__device__ __forceinline__ float ex2f(float x) {
    float y;
    asm("ex2.approx.f32 %0, %1;" : "=f"(y) : "f"(x));
    return y;
}

// ---------------------------------------------------------------------------
// Kernel 0: W [1024,128] fp32 -> transposed single fp16 [z][128][1024]
// ---------------------------------------------------------------------------
__global__ __launch_bounds__(256) void convert_w_kernel(
    const float* __restrict__ Wq, const float* __restrict__ Wk,
    const float* __restrict__ Wv)
{
    int z = blockIdx.y;
    const float* W = (z == 0) ? Wq : (z == 1) ? Wk : Wv;
    int idx = blockIdx.x * 256 + threadIdx.x;
    int k = idx >> 7, n = idx & 127;
    g_wt[(size_t)(z * H_ + n) * D_ + k] = __float2half_rn(W[idx]);
}

// ---------------------------------------------------------------------------
// Kernel 1: QKV projection, fp16 2-term (A split, W single).
// CTA: 128x128, 8 warps, grid interleave (m*3+z) for L2 A-reuse, 2 CTAs/SM.
// ---------------------------------------------------------------------------
#define KST 144
#define QA_HI 0
#define QA_LO 18432
#define QW    36864
#define QKV_SMEM 55296

__global__ __launch_bounds__(256, 2) void qkv_gemm(const float* __restrict__ A)
{
    extern __shared__ char smc[];
    const uint32_t sb = smem_u32(smc);
    const int tid = threadIdx.x, lane = tid & 31, wid = tid >> 5;
    const int wm = wid >> 1, wn = wid & 1;
    const int m0 = (blockIdx.x / 3) * 128, z = blockIdx.x % 3;
    const int g = lane >> 2, tg = lane & 3;

    const __half* wt = g_wt + (size_t)z * H_ * D_;

    float acc[2][8][4];
    #pragma unroll
    for (int a = 0; a < 2; a++)
        #pragma unroll
        for (int b = 0; b < 8; b++)
            #pragma unroll
            for (int c = 0; c < 4; c++) acc[a][b][c] = 0.f;

    for (int ch = 0; ch < 16; ch++) {
        const int k0 = ch * 64;
        // W single fp16 via cp.async
        #pragma unroll
        for (int i = 0; i < 4; i++) {
            const int rem = tid + i * 256;
            const int row = rem >> 3, c = rem & 7;
            cp16(sb + QW + row * KST + c * 16,
                 wt + (size_t)row * D_ + k0 + c * 8);
        }
        CP_COMMIT();

        // A fp32 LDG -> in-register 2-term split -> STS
        #pragma unroll
        for (int gi = 0; gi < 4; gi++) {
            const int u = tid + gi * 256;
            const int row = u >> 3, c8 = u & 7;
            const float* ap = A + (size_t)(m0 + row) * D_ + k0 + c8 * 8;
            float4 f0 = *(const float4*)ap;
            float4 f1 = *(const float4*)(ap + 4);
            uint32_t h0, l0, h1, l1, h2, l2, h3, l3;
            split2h(f0.x, f0.y, h0, l0);
            split2h(f0.z, f0.w, h1, l1);
            split2h(f1.x, f1.y, h2, l2);
            split2h(f1.z, f1.w, h3, l3);
            *(uint4*)(smc + QA_HI + row * KST + c8 * 16) = make_uint4(h0, h1, h2, h3);
            *(uint4*)(smc + QA_LO + row * KST + c8 * 16) = make_uint4(l0, l1, l2, l3);
        }
        CP_WAIT0();
        __syncthreads();

        #pragma unroll
        for (int s = 0; s < 4; s++) {
            uint32_t ah[2][4], al[2][4];
            #pragma unroll
            for (int mt = 0; mt < 2; mt++) {
                uint32_t ar = (uint32_t)((wm * 32 + mt * 16 + (lane & 15)) * KST
                               + (s * 16 + (lane >> 4) * 8) * 2);
                ldsm_x4(ah[mt], sb + QA_HI + ar);
                ldsm_x4(al[mt], sb + QA_LO + ar);
            }
            uint32_t bw[4][4];
            #pragma unroll
            for (int p = 0; p < 4; p++) {
                uint32_t br = (uint32_t)((wn * 64 + p * 16 + (lane >> 4) * 8 + (lane & 7)) * KST
                               + (s * 16 + ((lane >> 3) & 1) * 8) * 2);
                ldsm_x4(bw[p], sb + QW + br);
            }
            #pragma unroll
            for (int p = 0; p < 4; p++)
                #pragma unroll
                for (int mt = 0; mt < 2; mt++) {
                    mma16816(acc[mt][2*p],   ah[mt], bw[p]);
                    mma16816(acc[mt][2*p+1], ah[mt], bw[p] + 2);
                }
            #pragma unroll
            for (int p = 0; p < 4; p++)
                #pragma unroll
                for (int mt = 0; mt < 2; mt++) {
                    mma16816(acc[mt][2*p],   al[mt], bw[p]);
                    mma16816(acc[mt][2*p+1], al[mt], bw[p] + 2);
                }
        }
        __syncthreads();
    }

    // Q gets 1/sqrt(H)*log2(e) folded in (softmax runs in exp2 domain)
    const float scl = (z == 0)
        ? (0.0883883476483184405f * 1.4426950408889634f) : 1.0f;

    #pragma unroll
    for (int mt = 0; mt < 2; mt++)
        #pragma unroll
        for (int nt = 0; nt < 8; nt++) {
            float c0 = acc[mt][nt][0] * scl, c1 = acc[mt][nt][1] * scl;
            float c2 = acc[mt][nt][2] * scl, c3 = acc[mt][nt][3] * scl;
            int r0  = m0 + wm * 32 + mt * 16 + g;
            int col = wn * 64 + nt * 8 + tg * 2;
            if (z == 0) {
                uint32_t h01, l01, h23, l23;
                split2h(c0, c1, h01, l01);
                split2h(c2, c3, h23, l23);
                *(uint32_t*)(g_qh + (size_t)r0 * H_ + col)       = h01;
                *(uint32_t*)(g_ql + (size_t)r0 * H_ + col)       = l01;
                *(uint32_t*)(g_qh + (size_t)(r0 + 8) * H_ + col) = h23;
                *(uint32_t*)(g_ql + (size_t)(r0 + 8) * H_ + col) = l23;
            } else {
                __half* dst = (z == 1) ? g_k : g_v;
                *(uint32_t*)(dst + (size_t)r0 * H_ + col)       = pack2h(c0, c1);
                *(uint32_t*)(dst + (size_t)(r0 + 8) * H_ + col) = pack2h(c2, c3);
            }
        }
}

// ---------------------------------------------------------------------------
// Kernel 2: causal flash attention, fp16.  CTA = 128 queries, 8 warps,
// key tiles of 64, Q 2-term fragments in registers, K/V single fp16,
// P 2-term in-register, 2-stage K/V pipeline, exp2 softmax.
// ---------------------------------------------------------------------------
#define QS 272
#define ASTG  34816              // K buf + V buf, each 64 x 272
#define AK 0
#define AV 17408
#define ATT_SMEM (2*ASTG)        // 69632

__global__ __launch_bounds__(256, 1) void attn_mma(float* __restrict__ out)
{
    extern __shared__ char smc[];
    const uint32_t sb = smem_u32(smc);
    const int tid = threadIdx.x, lane = tid & 31, w = tid >> 5;
    const int b  = blockIdx.y;
    const int it = 15 - blockIdx.x;          // heavy tiles first
    const int q0 = it * 128;
    const int jmax = 2 * it + 1;
    const int g = lane >> 2, tg = lane & 3;
    const size_t base = (size_t)b * S_ * H_;

    #define ATT_ISSUE_KV(j, st) do {                                          \
        const int t0_ = (j) * 64;                                             \
        const uint32_t s0_ = sb + (st) * ASTG;                                \
        _Pragma("unroll")                                                     \
        for (int i = 0; i < 8; i++) {                                         \
            const int buf = i >> 2;                                           \
            const int rem = tid + (i & 3) * 256;                              \
            const int row = rem >> 4, c = rem & 15;                           \
            uint32_t d = s0_ + buf * 17408 + row * QS + c * 16;               \
            const __half* src = (buf == 0 ? g_k : g_v) + base                 \
                                + (size_t)(t0_ + row) * H_ + c * 8;           \
            cp16(d, src);                                                     \
        }                                                                     \
    } while (0)

    // ---- stage Q (2-term) into both stage areas, capture fragments ----
    #pragma unroll
    for (int i = 0; i < 16; i++) {
        const int buf = i >> 3;
        const int rem = tid + (i & 7) * 256;
        const int row = rem >> 4, c = rem & 15;
        uint32_t d = sb + buf * 34816 + row * QS + c * 16;
        const __half* src = (buf == 0 ? g_qh : g_ql) + base
                            + (size_t)(q0 + row) * H_ + c * 8;
        cp16(d, src);
    }
    CP_COMMIT(); CP_WAIT0();
    __syncthreads();
    uint32_t qh[8][4], ql[8][4];
    #pragma unroll
    for (int ks = 0; ks < 8; ks++) {
        uint32_t ar = (uint32_t)((w * 16 + (lane & 15)) * QS
                       + (ks * 16 + (lane >> 4) * 8) * 2);
        ldsm_x4(qh[ks], sb + ar);
        ldsm_x4(ql[ks], sb + 34816 + ar);
    }
    __syncthreads();                       // Q staging dead; stages reusable

    ATT_ISSUE_KV(0, 0); CP_COMMIT();

    float o[16][4];
    #pragma unroll
    for (int f = 0; f < 16; f++)
        #pragma unroll
        for (int c = 0; c < 4; c++) o[f][c] = 0.f;
    float m0r = -INFINITY, m1r = -INFINITY, l0 = 0.f, l1 = 0.f;

    for (int j = 0; j <= jmax; j++) {
        if (j < jmax) { ATT_ISSUE_KV(j + 1, (j + 1) & 1); CP_COMMIT(); CP_WAIT1(); }
        else CP_WAIT0();
        __syncthreads();

        const int t0 = j * 64;
        const uint32_t stb = sb + (j & 1) * ASTG;

        if (t0 <= q0 + w * 16 + 15) {      // warp has at least one unmasked row
            // ---- S = (qh+ql) K^T, K single fp16 ----
            float s[8][4];
            #pragma unroll
            for (int nt = 0; nt < 8; nt++)
                #pragma unroll
                for (int c = 0; c < 4; c++) s[nt][c] = 0.f;

            #pragma unroll
            for (int ks = 0; ks < 8; ks++) {
                uint32_t bk[4][4];
                #pragma unroll
                for (int p = 0; p < 4; p++) {
                    uint32_t br = (uint32_t)((p * 16 + (lane >> 4) * 8 + (lane & 7)) * QS
                                   + (ks * 16 + ((lane >> 3) & 1) * 8) * 2);
                    ldsm_x4(bk[p], stb + AK + br);
                }
                #pragma unroll
                for (int p = 0; p < 4; p++) {
                    mma16816(s[2*p],   qh[ks], bk[p]);
                    mma16816(s[2*p+1], qh[ks], bk[p] + 2);
                }
                #pragma unroll
                for (int p = 0; p < 4; p++) {
                    mma16816(s[2*p],   ql[ks], bk[p]);
                    mma16816(s[2*p+1], ql[ks], bk[p] + 2);
                }
            }

            // ---- causal mask (only near diagonal) ----
            if (j >= jmax - 1) {
                int r0 = q0 + w * 16 + g, r1 = r0 + 8;
                #pragma unroll
                for (int nt = 0; nt < 8; nt++) {
                    int kc = t0 + nt * 8 + tg * 2;
                    if (kc     > r0) s[nt][0] = -INFINITY;
                    if (kc + 1 > r0) s[nt][1] = -INFINITY;
                    if (kc     > r1) s[nt][2] = -INFINITY;
                    if (kc + 1 > r1) s[nt][3] = -INFINITY;
                }
            }

            // ---- online softmax, exp2 domain ----
            float ml0 = -INFINITY, ml1 = -INFINITY;
            #pragma unroll
            for (int nt = 0; nt < 8; nt++) {
                ml0 = fmaxf(ml0, fmaxf(s[nt][0], s[nt][1]));
                ml1 = fmaxf(ml1, fmaxf(s[nt][2], s[nt][3]));
            }
            #pragma unroll
            for (int ofs = 1; ofs <= 2; ofs <<= 1) {
                ml0 = fmaxf(ml0, __shfl_xor_sync(0xffffffffu, ml0, ofs));
                ml1 = fmaxf(ml1, __shfl_xor_sync(0xffffffffu, ml1, ofs));
            }
            float mn0 = fmaxf(m0r, ml0), mn1 = fmaxf(m1r, ml1);
            float a0 = ex2f(m0r - mn0), a1 = ex2f(m1r - mn1);
            m0r = mn0; m1r = mn1;

            float rs0 = 0.f, rs1 = 0.f;
            #pragma unroll
            for (int nt = 0; nt < 8; nt++) {
                s[nt][0] = ex2f(s[nt][0] - mn0); rs0 += s[nt][0];
                s[nt][1] = ex2f(s[nt][1] - mn0); rs0 += s[nt][1];
                s[nt][2] = ex2f(s[nt][2] - mn1); rs1 += s[nt][2];
                s[nt][3] = ex2f(s[nt][3] - mn1); rs1 += s[nt][3];
            }
            l0 = l0 * a0 + rs0;              // deferred cross-lane reduction
            l1 = l1 * a1 + rs1;
            #pragma unroll
            for (int f = 0; f < 16; f++) {
                o[f][0] *= a0; o[f][1] *= a0;
                o[f][2] *= a1; o[f][3] *= a1;
            }

            // ---- pack P (2-term fp16) ----
            uint32_t ph[4][4], pl[4][4];
            #pragma unroll
            for (int s4 = 0; s4 < 4; s4++) {
                split2h(s[2*s4][0],   s[2*s4][1],   ph[s4][0], pl[s4][0]);
                split2h(s[2*s4][2],   s[2*s4][3],   ph[s4][1], pl[s4][1]);
                split2h(s[2*s4+1][0], s[2*s4+1][1], ph[s4][2], pl[s4][2]);
                split2h(s[2*s4+1][2], s[2*s4+1][3], ph[s4][3], pl[s4][3]);
            }

            // ---- O += P V, V single fp16 (term-major, half-N groups) ----
            #pragma unroll
            for (int s4 = 0; s4 < 4; s4++) {
                #pragma unroll
                for (int half = 0; half < 2; half++) {
                    uint32_t vv[4][4];
                    #pragma unroll
                    for (int p4 = 0; p4 < 4; p4++) {
                        int p = half * 4 + p4;
                        uint32_t vr = (uint32_t)((s4 * 16 + (lane & 7) + ((lane >> 3) & 1) * 8) * QS
                                       + (p * 2 + (lane >> 4)) * 16);
                        ldsm_x4_t(vv[p4], stb + AV + vr);
                    }
                    #pragma unroll
                    for (int p4 = 0; p4 < 4; p4++) {
                        int p = half * 4 + p4;
                        mma16816(o[2*p],   ph[s4], vv[p4]);
                        mma16816(o[2*p+1], ph[s4], vv[p4] + 2);
                    }
                    #pragma unroll
                    for (int p4 = 0; p4 < 4; p4++) {
                        int p = half * 4 + p4;
                        mma16816(o[2*p],   pl[s4], vv[p4]);
                        mma16816(o[2*p+1], pl[s4], vv[p4] + 2);
                    }
                }
            }
        }
        __syncthreads();
    }

    // ---- final cross-lane sum reduction, normalize + store ----
    #pragma unroll
    for (int ofs = 1; ofs <= 2; ofs <<= 1) {
        l0 += __shfl_xor_sync(0xffffffffu, l0, ofs);
        l1 += __shfl_xor_sync(0xffffffffu, l1, ofs);
    }
    float i0 = 1.f / l0, i1 = 1.f / l1;
    int r0 = q0 + w * 16 + g;
    #pragma unroll
    for (int f = 0; f < 16; f++) {
        float2 v0 = make_float2(o[f][0] * i0, o[f][1] * i0);
        float2 v1 = make_float2(o[f][2] * i1, o[f][3] * i1);
        *(float2*)(out + base + (size_t)r0 * H_ + f * 8 + tg * 2)       = v0;
        *(float2*)(out + base + (size_t)(r0 + 8) * H_ + f * 8 + tg * 2) = v1;
    }
}

// ---------------------------------------------------------------------------
extern "C" void kernel_launch(void* const* d_in, const int* in_sizes, int n_in,
                              void* d_out, int out_size)
{
    const float* input = (const float*)d_in[0];
    const float* Wq    = (const float*)d_in[1];
    const float* Wk    = (const float*)d_in[2];
    const float* Wv    = (const float*)d_in[3];
    float* out = (float*)d_out;

    cudaFuncSetAttribute(qkv_gemm, cudaFuncAttributeMaxDynamicSharedMemorySize, QKV_SMEM);
    cudaFuncSetAttribute(attn_mma, cudaFuncAttributeMaxDynamicSharedMemorySize, ATT_SMEM);

    convert_w_kernel<<<dim3(512, 3), 256>>>(Wq, Wk, Wv);
    qkv_gemm<<<dim3(3 * M_TOT / 128, 1, 1), 256, QKV_SMEM>>>(input);
    attn_mma<<<dim3(16, B_), 256, ATT_SMEM>>>(out);
}

// round 9
// speedup vs baseline: 1.9841x; 1.2012x over previous
#include <cuda_runtime.h>
#include <cuda_fp16.h>
#include <cstdint>

#define B_ 16
#define S_ 2048
#define D_ 1024
#define H_ 128
#define M_TOT (B_*S_)

// ---------------- scratch (__device__ globals; allocation-free rule) -------
__device__ __half g_wt[3 * H_ * D_];             // W single fp16, [z][n][k]
__device__ __half g_q[M_TOT * H_];               // Q single (scaled)
__device__ __half g_k[M_TOT * H_];               // K single
__device__ __half g_v[M_TOT * H_];               // V single

// ---------------- helpers (sm_80-baseline, family-target safe) -------------
__device__ __forceinline__ uint32_t smem_u32(const void* p) {
    uint32_t a;
    asm("{ .reg .u64 t; cvta.to.shared.u64 t, %1; cvt.u32.u64 %0, t; }"
        : "=r"(a) : "l"(p));
    return a;
}
__device__ __forceinline__ void cp16(uint32_t dst, const void* src) {
    asm volatile("cp.async.cg.shared.global [%0], [%1], 16;" :: "r"(dst), "l"(src));
}
#define CP_COMMIT() asm volatile("cp.async.commit_group;" ::: "memory")
#define CP_WAIT0()  asm volatile("cp.async.wait_group 0;" ::: "memory")
#define CP_WAIT1()  asm volatile("cp.async.wait_group 1;" ::: "memory")

__device__ __forceinline__ void ldsm_x4(uint32_t r[4], uint32_t addr) {
    asm volatile("ldmatrix.sync.aligned.m8n8.x4.shared.b16 {%0,%1,%2,%3}, [%4];"
        : "=r"(r[0]), "=r"(r[1]), "=r"(r[2]), "=r"(r[3]) : "r"(addr));
}
__device__ __forceinline__ void ldsm_x4_t(uint32_t r[4], uint32_t addr) {
    asm volatile("ldmatrix.sync.aligned.m8n8.x4.trans.shared.b16 {%0,%1,%2,%3}, [%4];"
        : "=r"(r[0]), "=r"(r[1]), "=r"(r[2]), "=r"(r[3]) : "r"(addr));
}
__device__ __forceinline__ void mma16816(float c[4], const uint32_t a[4],
                                         const uint32_t b[2]) {
    asm volatile("mma.sync.aligned.m16n8k16.row.col.f32.f16.f16.f32 "
        "{%0,%1,%2,%3}, {%4,%5,%6,%7}, {%8,%9}, {%0,%1,%2,%3};"
        : "+f"(c[0]), "+f"(c[1]), "+f"(c[2]), "+f"(c[3])
        : "r"(a[0]), "r"(a[1]), "r"(a[2]), "r"(a[3]), "r"(b[0]), "r"(b[1]));
}
__device__ __forceinline__ void split2h(float x0, float x1, uint32_t& h, uint32_t& l) {
    __half h0 = __float2half_rn(x0), h1 = __float2half_rn(x1);
    __half2 hp = __halves2half2(h0, h1);
    h = *(uint32_t*)&hp;
    __half l0 = __float2half_rn(x0 - __half2float(h0));
    __half l1 = __float2half_rn(x1 - __half2float(h1));
    __half2 lp = __halves2half2(l0, l1);
    l = *(uint32_t*)&lp;
}
__device__ __forceinline__ uint32_t pack2h(float x0, float x1) {
    __half2 p = __floats2half2_rn(x0, x1);
    return *(uint32_t*)&p;
}
__device__ __forceinline__ float ex2f(float x) {
    float y;
    asm("ex2.approx.f32 %0, %1;" : "=f"(y) : "f"(x));
    return y;
}

// ---------------------------------------------------------------------------
// Kernel 0: W [1024,128] fp32 -> transposed single fp16 [z][128][1024]
// ---------------------------------------------------------------------------
__global__ __launch_bounds__(256) void convert_w_kernel(
    const float* __restrict__ Wq, const float* __restrict__ Wk,
    const float* __restrict__ Wv)
{
    int z = blockIdx.y;
    const float* W = (z == 0) ? Wq : (z == 1) ? Wk : Wv;
    int idx = blockIdx.x * 256 + threadIdx.x;
    int k = idx >> 7, n = idx & 127;
    g_wt[(size_t)(z * H_ + n) * D_ + k] = __float2half_rn(W[idx]);
}

// ---------------------------------------------------------------------------
// Kernel 1: QKV projection, fp16 2-term (A split, W single).
// CTA: 128x128, 8 warps, grid interleave (m*3+z) for L2 A-reuse, 2 CTAs/SM.
// ---------------------------------------------------------------------------
#define KST 144
#define QA_HI 0
#define QA_LO 18432
#define QW    36864
#define QKV_SMEM 55296

__global__ __launch_bounds__(256, 2) void qkv_gemm(const float* __restrict__ A)
{
    extern __shared__ char smc[];
    const uint32_t sb = smem_u32(smc);
    const int tid = threadIdx.x, lane = tid & 31, wid = tid >> 5;
    const int wm = wid >> 1, wn = wid & 1;
    const int m0 = (blockIdx.x / 3) * 128, z = blockIdx.x % 3;
    const int g = lane >> 2, tg = lane & 3;

    const __half* wt = g_wt + (size_t)z * H_ * D_;

    float acc[2][8][4];
    #pragma unroll
    for (int a = 0; a < 2; a++)
        #pragma unroll
        for (int b = 0; b < 8; b++)
            #pragma unroll
            for (int c = 0; c < 4; c++) acc[a][b][c] = 0.f;

    for (int ch = 0; ch < 16; ch++) {
        const int k0 = ch * 64;
        // W single fp16 via cp.async
        #pragma unroll
        for (int i = 0; i < 4; i++) {
            const int rem = tid + i * 256;
            const int row = rem >> 3, c = rem & 7;
            cp16(sb + QW + row * KST + c * 16,
                 wt + (size_t)row * D_ + k0 + c * 8);
        }
        CP_COMMIT();

        // A fp32 LDG -> in-register 2-term split -> STS
        #pragma unroll
        for (int gi = 0; gi < 4; gi++) {
            const int u = tid + gi * 256;
            const int row = u >> 3, c8 = u & 7;
            const float* ap = A + (size_t)(m0 + row) * D_ + k0 + c8 * 8;
            float4 f0 = *(const float4*)ap;
            float4 f1 = *(const float4*)(ap + 4);
            uint32_t h0, l0, h1, l1, h2, l2, h3, l3;
            split2h(f0.x, f0.y, h0, l0);
            split2h(f0.z, f0.w, h1, l1);
            split2h(f1.x, f1.y, h2, l2);
            split2h(f1.z, f1.w, h3, l3);
            *(uint4*)(smc + QA_HI + row * KST + c8 * 16) = make_uint4(h0, h1, h2, h3);
            *(uint4*)(smc + QA_LO + row * KST + c8 * 16) = make_uint4(l0, l1, l2, l3);
        }
        CP_WAIT0();
        __syncthreads();

        #pragma unroll
        for (int s = 0; s < 4; s++) {
            uint32_t ah[2][4], al[2][4];
            #pragma unroll
            for (int mt = 0; mt < 2; mt++) {
                uint32_t ar = (uint32_t)((wm * 32 + mt * 16 + (lane & 15)) * KST
                               + (s * 16 + (lane >> 4) * 8) * 2);
                ldsm_x4(ah[mt], sb + QA_HI + ar);
                ldsm_x4(al[mt], sb + QA_LO + ar);
            }
            uint32_t bw[4][4];
            #pragma unroll
            for (int p = 0; p < 4; p++) {
                uint32_t br = (uint32_t)((wn * 64 + p * 16 + (lane >> 4) * 8 + (lane & 7)) * KST
                               + (s * 16 + ((lane >> 3) & 1) * 8) * 2);
                ldsm_x4(bw[p], sb + QW + br);
            }
            #pragma unroll
            for (int p = 0; p < 4; p++)
                #pragma unroll
                for (int mt = 0; mt < 2; mt++) {
                    mma16816(acc[mt][2*p],   ah[mt], bw[p]);
                    mma16816(acc[mt][2*p+1], ah[mt], bw[p] + 2);
                }
            #pragma unroll
            for (int p = 0; p < 4; p++)
                #pragma unroll
                for (int mt = 0; mt < 2; mt++) {
                    mma16816(acc[mt][2*p],   al[mt], bw[p]);
                    mma16816(acc[mt][2*p+1], al[mt], bw[p] + 2);
                }
        }
        __syncthreads();
    }

    // Q gets 1/sqrt(H)*log2(e) folded in (softmax runs in exp2 domain)
    const float scl = (z == 0)
        ? (0.0883883476483184405f * 1.4426950408889634f) : 1.0f;
    __half* dst = (z == 0) ? g_q : (z == 1) ? g_k : g_v;

    #pragma unroll
    for (int mt = 0; mt < 2; mt++)
        #pragma unroll
        for (int nt = 0; nt < 8; nt++) {
            float c0 = acc[mt][nt][0] * scl, c1 = acc[mt][nt][1] * scl;
            float c2 = acc[mt][nt][2] * scl, c3 = acc[mt][nt][3] * scl;
            int r0  = m0 + wm * 32 + mt * 16 + g;
            int col = wn * 64 + nt * 8 + tg * 2;
            *(uint32_t*)(dst + (size_t)r0 * H_ + col)       = pack2h(c0, c1);
            *(uint32_t*)(dst + (size_t)(r0 + 8) * H_ + col) = pack2h(c2, c3);
        }
}

// ---------------------------------------------------------------------------
// Kernel 2: causal flash attention, all-single fp16 operands.
// CTA = 128 queries, 8 warps, key tiles of 64, Q fragments in registers,
// 2-stage K/V pipeline, exp2 softmax, deferred row-sum reduction.
// ---------------------------------------------------------------------------
#define QS 272
#define ASTG  34816              // K buf + V buf, each 64 x 272
#define AK 0
#define AV 17408
#define ATT_SMEM (2*ASTG)        // 69632

__global__ __launch_bounds__(256, 1) void attn_mma(float* __restrict__ out)
{
    extern __shared__ char smc[];
    const uint32_t sb = smem_u32(smc);
    const int tid = threadIdx.x, lane = tid & 31, w = tid >> 5;
    const int b  = blockIdx.y;
    const int it = 15 - blockIdx.x;          // heavy tiles first
    const int q0 = it * 128;
    const int jmax = 2 * it + 1;
    const int g = lane >> 2, tg = lane & 3;
    const size_t base = (size_t)b * S_ * H_;

    #define ATT_ISSUE_KV(j, st) do {                                          \
        const int t0_ = (j) * 64;                                             \
        const uint32_t s0_ = sb + (st) * ASTG;                                \
        _Pragma("unroll")                                                     \
        for (int i = 0; i < 8; i++) {                                         \
            const int buf = i >> 2;                                           \
            const int rem = tid + (i & 3) * 256;                              \
            const int row = rem >> 4, c = rem & 15;                           \
            uint32_t d = s0_ + buf * 17408 + row * QS + c * 16;               \
            const __half* src = (buf == 0 ? g_k : g_v) + base                 \
                                + (size_t)(t0_ + row) * H_ + c * 8;           \
            cp16(d, src);                                                     \
        }                                                                     \
    } while (0)

    // ---- stage Q (128x128 fp16, single term), capture fragments ----
    #pragma unroll
    for (int i = 0; i < 8; i++) {
        const int rem = tid + i * 256;
        const int row = rem >> 4, c = rem & 15;
        cp16(sb + row * QS + c * 16,
             g_q + base + (size_t)(q0 + row) * H_ + c * 8);
    }
    CP_COMMIT(); CP_WAIT0();
    __syncthreads();
    uint32_t qf[8][4];
    #pragma unroll
    for (int ks = 0; ks < 8; ks++) {
        uint32_t ar = (uint32_t)((w * 16 + (lane & 15)) * QS
                       + (ks * 16 + (lane >> 4) * 8) * 2);
        ldsm_x4(qf[ks], sb + ar);
    }
    __syncthreads();                       // Q staging dead; stages reusable

    ATT_ISSUE_KV(0, 0); CP_COMMIT();

    float o[16][4];
    #pragma unroll
    for (int f = 0; f < 16; f++)
        #pragma unroll
        for (int c = 0; c < 4; c++) o[f][c] = 0.f;
    float m0r = -INFINITY, m1r = -INFINITY, l0 = 0.f, l1 = 0.f;

    for (int j = 0; j <= jmax; j++) {
        if (j < jmax) { ATT_ISSUE_KV(j + 1, (j + 1) & 1); CP_COMMIT(); CP_WAIT1(); }
        else CP_WAIT0();
        __syncthreads();

        const int t0 = j * 64;
        const uint32_t stb = sb + (j & 1) * ASTG;

        if (t0 <= q0 + w * 16 + 15) {      // warp has at least one unmasked row
            // ---- S = Q K^T, single term ----
            float s[8][4];
            #pragma unroll
            for (int nt = 0; nt < 8; nt++)
                #pragma unroll
                for (int c = 0; c < 4; c++) s[nt][c] = 0.f;

            #pragma unroll
            for (int ks = 0; ks < 8; ks++) {
                uint32_t bk[4][4];
                #pragma unroll
                for (int p = 0; p < 4; p++) {
                    uint32_t br = (uint32_t)((p * 16 + (lane >> 4) * 8 + (lane & 7)) * QS
                                   + (ks * 16 + ((lane >> 3) & 1) * 8) * 2);
                    ldsm_x4(bk[p], stb + AK + br);
                }
                #pragma unroll
                for (int p = 0; p < 4; p++) {
                    mma16816(s[2*p],   qf[ks], bk[p]);
                    mma16816(s[2*p+1], qf[ks], bk[p] + 2);
                }
            }

            // ---- causal mask (only near diagonal) ----
            if (j >= jmax - 1) {
                int r0 = q0 + w * 16 + g, r1 = r0 + 8;
                #pragma unroll
                for (int nt = 0; nt < 8; nt++) {
                    int kc = t0 + nt * 8 + tg * 2;
                    if (kc     > r0) s[nt][0] = -INFINITY;
                    if (kc + 1 > r0) s[nt][1] = -INFINITY;
                    if (kc     > r1) s[nt][2] = -INFINITY;
                    if (kc + 1 > r1) s[nt][3] = -INFINITY;
                }
            }

            // ---- online softmax, exp2 domain ----
            float ml0 = -INFINITY, ml1 = -INFINITY;
            #pragma unroll
            for (int nt = 0; nt < 8; nt++) {
                ml0 = fmaxf(ml0, fmaxf(s[nt][0], s[nt][1]));
                ml1 = fmaxf(ml1, fmaxf(s[nt][2], s[nt][3]));
            }
            #pragma unroll
            for (int ofs = 1; ofs <= 2; ofs <<= 1) {
                ml0 = fmaxf(ml0, __shfl_xor_sync(0xffffffffu, ml0, ofs));
                ml1 = fmaxf(ml1, __shfl_xor_sync(0xffffffffu, ml1, ofs));
            }
            float mn0 = fmaxf(m0r, ml0), mn1 = fmaxf(m1r, ml1);
            float a0 = ex2f(m0r - mn0), a1 = ex2f(m1r - mn1);
            m0r = mn0; m1r = mn1;

            float rs0 = 0.f, rs1 = 0.f;
            #pragma unroll
            for (int nt = 0; nt < 8; nt++) {
                s[nt][0] = ex2f(s[nt][0] - mn0); rs0 += s[nt][0];
                s[nt][1] = ex2f(s[nt][1] - mn0); rs0 += s[nt][1];
                s[nt][2] = ex2f(s[nt][2] - mn1); rs1 += s[nt][2];
                s[nt][3] = ex2f(s[nt][3] - mn1); rs1 += s[nt][3];
            }
            l0 = l0 * a0 + rs0;              // deferred cross-lane reduction
            l1 = l1 * a1 + rs1;
            #pragma unroll
            for (int f = 0; f < 16; f++) {
                o[f][0] *= a0; o[f][1] *= a0;
                o[f][2] *= a1; o[f][3] *= a1;
            }

            // ---- pack P (single fp16) ----
            uint32_t pf[4][4];
            #pragma unroll
            for (int s4 = 0; s4 < 4; s4++) {
                pf[s4][0] = pack2h(s[2*s4][0],   s[2*s4][1]);
                pf[s4][1] = pack2h(s[2*s4][2],   s[2*s4][3]);
                pf[s4][2] = pack2h(s[2*s4+1][0], s[2*s4+1][1]);
                pf[s4][3] = pack2h(s[2*s4+1][2], s[2*s4+1][3]);
            }

            // ---- O += P V, single term (V via ldmatrix.trans) ----
            #pragma unroll
            for (int s4 = 0; s4 < 4; s4++) {
                #pragma unroll
                for (int half = 0; half < 2; half++) {
                    uint32_t vv[4][4];
                    #pragma unroll
                    for (int p4 = 0; p4 < 4; p4++) {
                        int p = half * 4 + p4;
                        uint32_t vr = (uint32_t)((s4 * 16 + (lane & 7) + ((lane >> 3) & 1) * 8) * QS
                                       + (p * 2 + (lane >> 4)) * 16);
                        ldsm_x4_t(vv[p4], stb + AV + vr);
                    }
                    #pragma unroll
                    for (int p4 = 0; p4 < 4; p4++) {
                        int p = half * 4 + p4;
                        mma16816(o[2*p],   pf[s4], vv[p4]);
                        mma16816(o[2*p+1], pf[s4], vv[p4] + 2);
                    }
                }
            }
        }
        __syncthreads();
    }

    // ---- final cross-lane sum reduction, normalize + store ----
    #pragma unroll
    for (int ofs = 1; ofs <= 2; ofs <<= 1) {
        l0 += __shfl_xor_sync(0xffffffffu, l0, ofs);
        l1 += __shfl_xor_sync(0xffffffffu, l1, ofs);
    }
    float i0 = 1.f / l0, i1 = 1.f / l1;
    int r0 = q0 + w * 16 + g;
    #pragma unroll
    for (int f = 0; f < 16; f++) {
        float2 v0 = make_float2(o[f][0] * i0, o[f][1] * i0);
        float2 v1 = make_float2(o[f][2] * i1, o[f][3] * i1);
        *(float2*)(out + base + (size_t)r0 * H_ + f * 8 + tg * 2)       = v0;
        *(float2*)(out + base + (size_t)(r0 + 8) * H_ + f * 8 + tg * 2) = v1;
    }
}

// ---------------------------------------------------------------------------
extern "C" void kernel_launch(void* const* d_in, const int* in_sizes, int n_in,
                              void* d_out, int out_size)
{
    const float* input = (const float*)d_in[0];
    const float* Wq    = (const float*)d_in[1];
    const float* Wk    = (const float*)d_in[2];
    const float* Wv    = (const float*)d_in[3];
    float* out = (float*)d_out;

    cudaFuncSetAttribute(qkv_gemm, cudaFuncAttributeMaxDynamicSharedMemorySize, QKV_SMEM);
    cudaFuncSetAttribute(attn_mma, cudaFuncAttributeMaxDynamicSharedMemorySize, ATT_SMEM);

    convert_w_kernel<<<dim3(512, 3), 256>>>(Wq, Wk, Wv);
    qkv_gemm<<<dim3(3 * M_TOT / 128, 1, 1), 256, QKV_SMEM>>>(input);
    attn_mma<<<dim3(16, B_), 256, ATT_SMEM>>>(out);
}

// round 12
// speedup vs baseline: 2.4460x; 1.2328x over previous
#include <cuda_runtime.h>
#include <cuda_fp16.h>
#include <cstdint>

#define B_ 16
#define S_ 2048
#define D_ 1024
#define H_ 128
#define M_TOT (B_*S_)

// ---------------- scratch (__device__ globals; allocation-free rule) -------
__device__ __half g_wt[3 * H_ * D_];             // W single fp16, [z][n][k]
__device__ __half g_q[M_TOT * H_];               // Q single (scaled)
__device__ __half g_k[M_TOT * H_];               // K single
__device__ __half g_v[M_TOT * H_];               // V single

// ---------------- helpers (sm_80-baseline, family-target safe) -------------
__device__ __forceinline__ uint32_t smem_u32(const void* p) {
    uint32_t a;
    asm("{ .reg .u64 t; cvta.to.shared.u64 t, %1; cvt.u32.u64 %0, t; }"
        : "=r"(a) : "l"(p));
    return a;
}
__device__ __forceinline__ void cp16(uint32_t dst, const void* src) {
    asm volatile("cp.async.cg.shared.global [%0], [%1], 16;" :: "r"(dst), "l"(src));
}
#define CP_COMMIT() asm volatile("cp.async.commit_group;" ::: "memory")
#define CP_WAIT0()  asm volatile("cp.async.wait_group 0;" ::: "memory")
#define CP_WAIT1()  asm volatile("cp.async.wait_group 1;" ::: "memory")

__device__ __forceinline__ void ldsm_x4(uint32_t r[4], uint32_t addr) {
    asm volatile("ldmatrix.sync.aligned.m8n8.x4.shared.b16 {%0,%1,%2,%3}, [%4];"
        : "=r"(r[0]), "=r"(r[1]), "=r"(r[2]), "=r"(r[3]) : "r"(addr));
}
__device__ __forceinline__ void ldsm_x4_t(uint32_t r[4], uint32_t addr) {
    asm volatile("ldmatrix.sync.aligned.m8n8.x4.trans.shared.b16 {%0,%1,%2,%3}, [%4];"
        : "=r"(r[0]), "=r"(r[1]), "=r"(r[2]), "=r"(r[3]) : "r"(addr));
}
__device__ __forceinline__ void mma16816(float c[4], const uint32_t a[4],
                                         const uint32_t b[2]) {
    asm volatile("mma.sync.aligned.m16n8k16.row.col.f32.f16.f16.f32 "
        "{%0,%1,%2,%3}, {%4,%5,%6,%7}, {%8,%9}, {%0,%1,%2,%3};"
        : "+f"(c[0]), "+f"(c[1]), "+f"(c[2]), "+f"(c[3])
        : "r"(a[0]), "r"(a[1]), "r"(a[2]), "r"(a[3]), "r"(b[0]), "r"(b[1]));
}
__device__ __forceinline__ uint32_t pack2h(float x0, float x1) {
    __half2 p = __floats2half2_rn(x0, x1);
    return *(uint32_t*)&p;
}
__device__ __forceinline__ float ex2f(float x) {
    float y;
    asm("ex2.approx.f32 %0, %1;" : "=f"(y) : "f"(x));
    return y;
}

// ---------------------------------------------------------------------------
// Kernel 0: W [1024,128] fp32 -> transposed single fp16 [z][128][1024]
// ---------------------------------------------------------------------------
__global__ __launch_bounds__(256) void convert_w_kernel(
    const float* __restrict__ Wq, const float* __restrict__ Wk,
    const float* __restrict__ Wv)
{
    int z = blockIdx.y;
    const float* W = (z == 0) ? Wq : (z == 1) ? Wk : Wv;
    int idx = blockIdx.x * 256 + threadIdx.x;
    int k = idx >> 7, n = idx & 127;
    g_wt[(size_t)(z * H_ + n) * D_ + k] = __float2half_rn(W[idx]);
}

// ---------------------------------------------------------------------------
// Kernel 1: QKV projection, single fp16 both operands (A converted in-reg).
// CTA: 128x128, 8 warps, grid interleave (m*3+z) for L2 A-reuse, 2 CTAs/SM.
// ---------------------------------------------------------------------------
#define KST 144
#define QA 0
#define QW 18432
#define QKV_SMEM 36864

__global__ __launch_bounds__(256, 2) void qkv_gemm(const float* __restrict__ A)
{
    extern __shared__ char smc[];
    const uint32_t sb = smem_u32(smc);
    const int tid = threadIdx.x, lane = tid & 31, wid = tid >> 5;
    const int wm = wid >> 1, wn = wid & 1;
    const int m0 = (blockIdx.x / 3) * 128, z = blockIdx.x % 3;
    const int g = lane >> 2, tg = lane & 3;

    const __half* wt = g_wt + (size_t)z * H_ * D_;

    float acc[2][8][4];
    #pragma unroll
    for (int a = 0; a < 2; a++)
        #pragma unroll
        for (int b = 0; b < 8; b++)
            #pragma unroll
            for (int c = 0; c < 4; c++) acc[a][b][c] = 0.f;

    for (int ch = 0; ch < 16; ch++) {
        const int k0 = ch * 64;
        // W single fp16 via cp.async
        #pragma unroll
        for (int i = 0; i < 4; i++) {
            const int rem = tid + i * 256;
            const int row = rem >> 3, c = rem & 7;
            cp16(sb + QW + row * KST + c * 16,
                 wt + (size_t)row * D_ + k0 + c * 8);
        }
        CP_COMMIT();

        // A fp32 LDG -> fp16 convert -> STS (single buffer)
        #pragma unroll
        for (int gi = 0; gi < 4; gi++) {
            const int u = tid + gi * 256;
            const int row = u >> 3, c8 = u & 7;
            const float* ap = A + (size_t)(m0 + row) * D_ + k0 + c8 * 8;
            float4 f0 = *(const float4*)ap;
            float4 f1 = *(const float4*)(ap + 4);
            uint4 hv = make_uint4(pack2h(f0.x, f0.y), pack2h(f0.z, f0.w),
                                  pack2h(f1.x, f1.y), pack2h(f1.z, f1.w));
            *(uint4*)(smc + QA + row * KST + c8 * 16) = hv;
        }
        CP_WAIT0();
        __syncthreads();

        #pragma unroll
        for (int s = 0; s < 4; s++) {
            uint32_t af[2][4];
            #pragma unroll
            for (int mt = 0; mt < 2; mt++) {
                uint32_t ar = (uint32_t)((wm * 32 + mt * 16 + (lane & 15)) * KST
                               + (s * 16 + (lane >> 4) * 8) * 2);
                ldsm_x4(af[mt], sb + QA + ar);
            }
            uint32_t bw[4][4];
            #pragma unroll
            for (int p = 0; p < 4; p++) {
                uint32_t br = (uint32_t)((wn * 64 + p * 16 + (lane >> 4) * 8 + (lane & 7)) * KST
                               + (s * 16 + ((lane >> 3) & 1) * 8) * 2);
                ldsm_x4(bw[p], sb + QW + br);
            }
            #pragma unroll
            for (int p = 0; p < 4; p++)
                #pragma unroll
                for (int mt = 0; mt < 2; mt++) {
                    mma16816(acc[mt][2*p],   af[mt], bw[p]);
                    mma16816(acc[mt][2*p+1], af[mt], bw[p] + 2);
                }
        }
        __syncthreads();
    }

    // Q gets 1/sqrt(H)*log2(e) folded in (softmax runs in exp2 domain)
    const float scl = (z == 0)
        ? (0.0883883476483184405f * 1.4426950408889634f) : 1.0f;
    __half* dst = (z == 0) ? g_q : (z == 1) ? g_k : g_v;

    #pragma unroll
    for (int mt = 0; mt < 2; mt++)
        #pragma unroll
        for (int nt = 0; nt < 8; nt++) {
            float c0 = acc[mt][nt][0] * scl, c1 = acc[mt][nt][1] * scl;
            float c2 = acc[mt][nt][2] * scl, c3 = acc[mt][nt][3] * scl;
            int r0  = m0 + wm * 32 + mt * 16 + g;
            int col = wn * 64 + nt * 8 + tg * 2;
            *(uint32_t*)(dst + (size_t)r0 * H_ + col)       = pack2h(c0, c1);
            *(uint32_t*)(dst + (size_t)(r0 + 8) * H_ + col) = pack2h(c2, c3);
        }
}

// ---------------------------------------------------------------------------
// Kernel 2: causal flash attention, all-single fp16 operands.
// CTA = 128 queries, 8 warps, key tiles of 64, Q fragments in registers,
// 2-stage K/V pipeline, exp2 softmax, deferred row-sum reduction.
// ---------------------------------------------------------------------------
#define QS 272
#define ASTG  34816              // K buf + V buf, each 64 x 272
#define AK 0
#define AV 17408
#define ATT_SMEM (2*ASTG)        // 69632

__global__ __launch_bounds__(256, 1) void attn_mma(float* __restrict__ out)
{
    extern __shared__ char smc[];
    const uint32_t sb = smem_u32(smc);
    const int tid = threadIdx.x, lane = tid & 31, w = tid >> 5;
    const int b  = blockIdx.y;
    const int it = 15 - blockIdx.x;          // heavy tiles first
    const int q0 = it * 128;
    const int jmax = 2 * it + 1;
    const int g = lane >> 2, tg = lane & 3;
    const size_t base = (size_t)b * S_ * H_;

    #define ATT_ISSUE_KV(j, st) do {                                          \
        const int t0_ = (j) * 64;                                             \
        const uint32_t s0_ = sb + (st) * ASTG;                                \
        _Pragma("unroll")                                                     \
        for (int i = 0; i < 8; i++) {                                         \
            const int buf = i >> 2;                                           \
            const int rem = tid + (i & 3) * 256;                              \
            const int row = rem >> 4, c = rem & 15;                           \
            uint32_t d = s0_ + buf * 17408 + row * QS + c * 16;               \
            const __half* src = (buf == 0 ? g_k : g_v) + base                 \
                                + (size_t)(t0_ + row) * H_ + c * 8;           \
            cp16(d, src);                                                     \
        }                                                                     \
    } while (0)

    // ---- stage Q (128x128 fp16, single term), capture fragments ----
    #pragma unroll
    for (int i = 0; i < 8; i++) {
        const int rem = tid + i * 256;
        const int row = rem >> 4, c = rem & 15;
        cp16(sb + row * QS + c * 16,
             g_q + base + (size_t)(q0 + row) * H_ + c * 8);
    }
    CP_COMMIT(); CP_WAIT0();
    __syncthreads();
    uint32_t qf[8][4];
    #pragma unroll
    for (int ks = 0; ks < 8; ks++) {
        uint32_t ar = (uint32_t)((w * 16 + (lane & 15)) * QS
                       + (ks * 16 + (lane >> 4) * 8) * 2);
        ldsm_x4(qf[ks], sb + ar);
    }
    __syncthreads();                       // Q staging dead; stages reusable

    ATT_ISSUE_KV(0, 0); CP_COMMIT();

    float o[16][4];
    #pragma unroll
    for (int f = 0; f < 16; f++)
        #pragma unroll
        for (int c = 0; c < 4; c++) o[f][c] = 0.f;
    float m0r = -INFINITY, m1r = -INFINITY, l0 = 0.f, l1 = 0.f;

    for (int j = 0; j <= jmax; j++) {
        if (j < jmax) { ATT_ISSUE_KV(j + 1, (j + 1) & 1); CP_COMMIT(); CP_WAIT1(); }
        else CP_WAIT0();
        __syncthreads();

        const int t0 = j * 64;
        const uint32_t stb = sb + (j & 1) * ASTG;

        if (t0 <= q0 + w * 16 + 15) {      // warp has at least one unmasked row
            // ---- S = Q K^T, single term ----
            float s[8][4];
            #pragma unroll
            for (int nt = 0; nt < 8; nt++)
                #pragma unroll
                for (int c = 0; c < 4; c++) s[nt][c] = 0.f;

            #pragma unroll
            for (int ks = 0; ks < 8; ks++) {
                uint32_t bk[4][4];
                #pragma unroll
                for (int p = 0; p < 4; p++) {
                    uint32_t br = (uint32_t)((p * 16 + (lane >> 4) * 8 + (lane & 7)) * QS
                                   + (ks * 16 + ((lane >> 3) & 1) * 8) * 2);
                    ldsm_x4(bk[p], stb + AK + br);
                }
                #pragma unroll
                for (int p = 0; p < 4; p++) {
                    mma16816(s[2*p],   qf[ks], bk[p]);
                    mma16816(s[2*p+1], qf[ks], bk[p] + 2);
                }
            }

            // ---- causal mask (only near diagonal) ----
            if (j >= jmax - 1) {
                int r0 = q0 + w * 16 + g, r1 = r0 + 8;
                #pragma unroll
                for (int nt = 0; nt < 8; nt++) {
                    int kc = t0 + nt * 8 + tg * 2;
                    if (kc     > r0) s[nt][0] = -INFINITY;
                    if (kc + 1 > r0) s[nt][1] = -INFINITY;
                    if (kc     > r1) s[nt][2] = -INFINITY;
                    if (kc + 1 > r1) s[nt][3] = -INFINITY;
                }
            }

            // ---- online softmax, exp2 domain ----
            float ml0 = -INFINITY, ml1 = -INFINITY;
            #pragma unroll
            for (int nt = 0; nt < 8; nt++) {
                ml0 = fmaxf(ml0, fmaxf(s[nt][0], s[nt][1]));
                ml1 = fmaxf(ml1, fmaxf(s[nt][2], s[nt][3]));
            }
            #pragma unroll
            for (int ofs = 1; ofs <= 2; ofs <<= 1) {
                ml0 = fmaxf(ml0, __shfl_xor_sync(0xffffffffu, ml0, ofs));
                ml1 = fmaxf(ml1, __shfl_xor_sync(0xffffffffu, ml1, ofs));
            }
            float mn0 = fmaxf(m0r, ml0), mn1 = fmaxf(m1r, ml1);
            float a0 = ex2f(m0r - mn0), a1 = ex2f(m1r - mn1);
            m0r = mn0; m1r = mn1;

            float rs0 = 0.f, rs1 = 0.f;
            #pragma unroll
            for (int nt = 0; nt < 8; nt++) {
                s[nt][0] = ex2f(s[nt][0] - mn0); rs0 += s[nt][0];
                s[nt][1] = ex2f(s[nt][1] - mn0); rs0 += s[nt][1];
                s[nt][2] = ex2f(s[nt][2] - mn1); rs1 += s[nt][2];
                s[nt][3] = ex2f(s[nt][3] - mn1); rs1 += s[nt][3];
            }
            l0 = l0 * a0 + rs0;              // deferred cross-lane reduction
            l1 = l1 * a1 + rs1;
            #pragma unroll
            for (int f = 0; f < 16; f++) {
                o[f][0] *= a0; o[f][1] *= a0;
                o[f][2] *= a1; o[f][3] *= a1;
            }

            // ---- pack P (single fp16) ----
            uint32_t pf[4][4];
            #pragma unroll
            for (int s4 = 0; s4 < 4; s4++) {
                pf[s4][0] = pack2h(s[2*s4][0],   s[2*s4][1]);
                pf[s4][1] = pack2h(s[2*s4][2],   s[2*s4][3]);
                pf[s4][2] = pack2h(s[2*s4+1][0], s[2*s4+1][1]);
                pf[s4][3] = pack2h(s[2*s4+1][2], s[2*s4+1][3]);
            }

            // ---- O += P V, single term (V via ldmatrix.trans) ----
            #pragma unroll
            for (int s4 = 0; s4 < 4; s4++) {
                #pragma unroll
                for (int half = 0; half < 2; half++) {
                    uint32_t vv[4][4];
                    #pragma unroll
                    for (int p4 = 0; p4 < 4; p4++) {
                        int p = half * 4 + p4;
                        uint32_t vr = (uint32_t)((s4 * 16 + (lane & 7) + ((lane >> 3) & 1) * 8) * QS
                                       + (p * 2 + (lane >> 4)) * 16);
                        ldsm_x4_t(vv[p4], stb + AV + vr);
                    }
                    #pragma unroll
                    for (int p4 = 0; p4 < 4; p4++) {
                        int p = half * 4 + p4;
                        mma16816(o[2*p],   pf[s4], vv[p4]);
                        mma16816(o[2*p+1], pf[s4], vv[p4] + 2);
                    }
                }
            }
        }
        __syncthreads();
    }

    // ---- final cross-lane sum reduction, normalize + store ----
    #pragma unroll
    for (int ofs = 1; ofs <= 2; ofs <<= 1) {
        l0 += __shfl_xor_sync(0xffffffffu, l0, ofs);
        l1 += __shfl_xor_sync(0xffffffffu, l1, ofs);
    }
    float i0 = 1.f / l0, i1 = 1.f / l1;
    int r0 = q0 + w * 16 + g;
    #pragma unroll
    for (int f = 0; f < 16; f++) {
        float2 v0 = make_float2(o[f][0] * i0, o[f][1] * i0);
        float2 v1 = make_float2(o[f][2] * i1, o[f][3] * i1);
        *(float2*)(out + base + (size_t)r0 * H_ + f * 8 + tg * 2)       = v0;
        *(float2*)(out + base + (size_t)(r0 + 8) * H_ + f * 8 + tg * 2) = v1;
    }
}

// ---------------------------------------------------------------------------
extern "C" void kernel_launch(void* const* d_in, const int* in_sizes, int n_in,
                              void* d_out, int out_size)
{
    const float* input = (const float*)d_in[0];
    const float* Wq    = (const float*)d_in[1];
    const float* Wk    = (const float*)d_in[2];
    const float* Wv    = (const float*)d_in[3];
    float* out = (float*)d_out;

    cudaFuncSetAttribute(qkv_gemm, cudaFuncAttributeMaxDynamicSharedMemorySize, QKV_SMEM);
    cudaFuncSetAttribute(attn_mma, cudaFuncAttributeMaxDynamicSharedMemorySize, ATT_SMEM);

    convert_w_kernel<<<dim3(512, 3), 256>>>(Wq, Wk, Wv);
    qkv_gemm<<<dim3(3 * M_TOT / 128, 1, 1), 256, QKV_SMEM>>>(input);
    attn_mma<<<dim3(16, B_), 256, ATT_SMEM>>>(out);
}